// round 7
// baseline (speedup 1.0000x reference)
#include <cuda_runtime.h>
#include <math.h>
#include <stdint.h>

// Problem constants
#define BB   8
#define SS   8192
#define DD   512
#define EE   16
#define DFFN 512
#define KCAP 1024
#define NTOK (BB*SS)
#define NGRP (BB*EE)

// Scratch — referenced ONLY inside device code
__device__ float g_aff [NGRP * SS];
__device__ int   g_idx [NGRP * KCAP];
__device__ float g_gate[NGRP * KCAP];
__device__ float g_h   [(size_t)NGRP * KCAP * DFFN];   // 256MB, tf32-rounded
__device__ float g_xt  [(size_t)NTOK * DD];            // 128MB, x tf32-rounded
__device__ float g_w1p [(size_t)EE * DD * DFFN];       // fragment-packed, tf32
__device__ float g_w2p [(size_t)EE * DFFN * DD];       // fragment-packed, tf32

__device__ __forceinline__ unsigned f2tf32(float f)
{
    unsigned r;
    asm("cvt.rna.tf32.f32 %0, %1;" : "=r"(r) : "f"(f));
    return r;
}
__device__ __forceinline__ float rtf(float f) { return __uint_as_float(f2tf32(f)); }

__device__ __forceinline__ void cpa16(uint32_t dst, const void* src)
{
    asm volatile("cp.async.cg.shared.global [%0], [%1], 16;\n" :: "r"(dst), "l"(src));
}
#define CP_COMMIT() asm volatile("cp.async.commit_group;\n" ::: "memory")
#define CP_WAIT0()  asm volatile("cp.async.wait_group 0;\n" ::: "memory")
#define CP_WAIT1()  asm volatile("cp.async.wait_group 1;\n" ::: "memory")

__device__ __forceinline__ uint32_t smem_u32(const void* p)
{
    uint32_t a;
    asm("{ .reg .u64 t; cvta.to.shared.u64 t, %1; cvt.u32.u64 %0, t; }" : "=r"(a) : "l"(p));
    return a;
}

__device__ __forceinline__ void mma_tf32(float* c, const unsigned* a,
                                         unsigned b0, unsigned b1)
{
    asm volatile(
        "mma.sync.aligned.m16n8k8.row.col.f32.tf32.tf32.f32 "
        "{%0,%1,%2,%3}, {%4,%5,%6,%7}, {%8,%9}, {%0,%1,%2,%3};\n"
        : "+f"(c[0]), "+f"(c[1]), "+f"(c[2]), "+f"(c[3])
        : "r"(a[0]), "r"(a[1]), "r"(a[2]), "r"(a[3]), "r"(b0), "r"(b1));
}

__device__ __forceinline__ float gelu_tanh(float v)
{
    float v3 = v * v * v;
    float t = tanhf(0.7978845608028654f * (v + 0.044715f * v3));
    return 0.5f * v * (1.f + t);
}

// ---------------------------------------------------------------------------
// Weight prepack: fragment-major, tf32-rounded.
// packed[(((e*32 + c)*64 + n8)*32 + lane)*4 + q] = w[e][k][n],
//   k = c*16 + (lane&3) + 4q,  n = n8*8 + (lane>>2)
// ---------------------------------------------------------------------------
__global__ void pack_w1(const float* __restrict__ src)
{
    size_t i = (size_t)blockIdx.x * 256 + threadIdx.x;  // one float4 each
    int lane = i & 31; size_t t = i >> 5;
    int n8 = t & 63; t >>= 6;
    int c = t & 31; int e = (int)(t >> 5);
    int k0 = c * 16 + (lane & 3);
    int n = n8 * 8 + (lane >> 2);
    const float* S = src + ((size_t)e * DD + k0) * DFFN + n;
    float4 v;
    v.x = rtf(S[0]);
    v.y = rtf(S[4 * DFFN]);
    v.z = rtf(S[8 * DFFN]);
    v.w = rtf(S[12 * DFFN]);
    ((float4*)g_w1p)[i] = v;
}
__global__ void pack_w2(const float* __restrict__ src)
{
    size_t i = (size_t)blockIdx.x * 256 + threadIdx.x;
    int lane = i & 31; size_t t = i >> 5;
    int n8 = t & 63; t >>= 6;
    int c = t & 31; int e = (int)(t >> 5);
    int k0 = c * 16 + (lane & 3);
    int n = n8 * 8 + (lane >> 2);
    const float* S = src + ((size_t)e * DFFN + k0) * DD + n;
    float4 v;
    v.x = rtf(S[0]);
    v.y = rtf(S[4 * DD]);
    v.z = rtf(S[8 * DD]);
    v.w = rtf(S[12 * DD]);
    ((float4*)g_w2p)[i] = v;
}

// ---------------------------------------------------------------------------
// Router — 4 tokens/warp, fused softmax + x->tf32
// ---------------------------------------------------------------------------
__global__ __launch_bounds__(256) void router2_kernel(
    const float4* __restrict__ x4, const float* __restrict__ gw)
{
    __shared__ float4 sgw4[EE][DD / 4];
    int tid = threadIdx.x;
    for (int i = tid; i < EE * (DD / 4); i += 256) {
        int e = i >> 7, dq = i & 127;
        float4 v;
        v.x = gw[(4 * dq + 0) * EE + e];
        v.y = gw[(4 * dq + 1) * EE + e];
        v.z = gw[(4 * dq + 2) * EE + e];
        v.w = gw[(4 * dq + 3) * EE + e];
        sgw4[e][dq] = v;
    }
    __syncthreads();

    int warp = tid >> 5, lane = tid & 31;
    int t0 = blockIdx.x * 32 + warp * 4;
    int b = t0 / SS;

    float acc[4][EE];
#pragma unroll
    for (int tt = 0; tt < 4; tt++)
#pragma unroll
        for (int e = 0; e < EE; e++) acc[tt][e] = 0.f;

#pragma unroll
    for (int q = 0; q < 4; q++) {
        int dq = lane + q * 32;
        float4 xv[4];
#pragma unroll
        for (int tt = 0; tt < 4; tt++)
            xv[tt] = x4[(size_t)(t0 + tt) * (DD / 4) + dq];
#pragma unroll
        for (int tt = 0; tt < 4; tt++) {
            float4 o;
            o.x = rtf(xv[tt].x); o.y = rtf(xv[tt].y);
            o.z = rtf(xv[tt].z); o.w = rtf(xv[tt].w);
            ((float4*)g_xt)[(size_t)(t0 + tt) * (DD / 4) + dq] = o;
        }
#pragma unroll
        for (int e = 0; e < EE; e++) {
            float4 w = sgw4[e][dq];
#pragma unroll
            for (int tt = 0; tt < 4; tt++) {
                acc[tt][e] = fmaf(xv[tt].x, w.x, acc[tt][e]);
                acc[tt][e] = fmaf(xv[tt].y, w.y, acc[tt][e]);
                acc[tt][e] = fmaf(xv[tt].z, w.z, acc[tt][e]);
                acc[tt][e] = fmaf(xv[tt].w, w.w, acc[tt][e]);
            }
        }
    }

#pragma unroll
    for (int tt = 0; tt < 4; tt++)
#pragma unroll
        for (int e = 0; e < EE; e++)
#pragma unroll
            for (int o = 16; o > 0; o >>= 1)
                acc[tt][e] += __shfl_xor_sync(0xffffffffu, acc[tt][e], o);

    int le = lane & 15;
#pragma unroll
    for (int tt = 0; tt < 4; tt++) {
        float m = acc[tt][0];
#pragma unroll
        for (int e = 1; e < EE; e++) m = fmaxf(m, acc[tt][e]);
        float v = expf(acc[tt][le] - m);
        float s = v;
#pragma unroll
        for (int o = 8; o > 0; o >>= 1)
            s += __shfl_xor_sync(0xffffffffu, s, o);
        if (lane < EE) {
            int srow = t0 + tt - b * SS;
            g_aff[((size_t)(b * EE + lane)) * SS + srow] = v * (1.f / s);
        }
    }
}

// ---------------------------------------------------------------------------
// Exact radix-select top-KCAP (unchanged)
// ---------------------------------------------------------------------------
__global__ __launch_bounds__(256) void topk_kernel()
{
    int g = blockIdx.x;
    const float* a = g_aff + (size_t)g * SS;
    int tid = threadIdx.x;

    __shared__ unsigned hist[256];
    __shared__ unsigned sPrefix, sMask, sRemain;

    if (tid == 0) { sPrefix = 0u; sMask = 0u; sRemain = KCAP; }
    __syncthreads();

    for (int pass = 3; pass >= 0; pass--) {
        for (int i = tid; i < 256; i += blockDim.x) hist[i] = 0u;
        __syncthreads();
        unsigned pfx = sPrefix, msk = sMask;
        int sh = pass * 8;
        for (int s = tid; s < SS; s += blockDim.x) {
            unsigned key = __float_as_uint(a[s]);
            if ((key & msk) == pfx)
                atomicAdd(&hist[(key >> sh) & 0xFFu], 1u);
        }
        __syncthreads();
        if (tid == 0) {
            unsigned need = sRemain, cum = 0;
            int d = 255;
            for (; d > 0; d--) {
                if (cum + hist[d] >= need) break;
                cum += hist[d];
            }
            sRemain = need - cum;
            sPrefix = pfx | ((unsigned)d << sh);
            sMask   = msk | (0xFFu << sh);
        }
        __syncthreads();
    }

    unsigned T = sPrefix;
    int kEq   = (int)sRemain;
    int cntGt = KCAP - kEq;

    __shared__ unsigned gtCnt;
    __shared__ int eqBase;
    __shared__ int warpEq[8];
    if (tid == 0) { gtCnt = 0u; eqBase = 0; }
    __syncthreads();

    int lane = tid & 31, warp = tid >> 5;
    int*   oIdx  = g_idx  + g * KCAP;
    float* oGate = g_gate + g * KCAP;

    for (int c = 0; c < SS / 256; c++) {
        int s = c * 256 + tid;
        float v = a[s];
        unsigned key = __float_as_uint(v);
        bool isGt = key > T, isEq = key == T;

        if (isGt) {
            unsigned p = atomicAdd(&gtCnt, 1u);
            oIdx[p] = s; oGate[p] = v;
        }
        unsigned bal = __ballot_sync(0xffffffffu, isEq);
        if (lane == 0) warpEq[warp] = __popc(bal);
        __syncthreads();
        if (isEq) {
            int r = eqBase;
#pragma unroll
            for (int w = 0; w < 8; w++) if (w < warp) r += warpEq[w];
            r += __popc(bal & ((1u << lane) - 1u));
            if (r < kEq) { oIdx[cntGt + r] = s; oGate[cntGt + r] = v; }
        }
        __syncthreads();
        if (tid == 0) {
            int tot = 0;
#pragma unroll
            for (int w = 0; w < 8; w++) tot += warpEq[w];
            eqBase += tot;
        }
        __syncthreads();
    }
}

// ---------------------------------------------------------------------------
// Zero output
// ---------------------------------------------------------------------------
__global__ void zero_kernel(float4* __restrict__ out, int n4)
{
    int i = blockIdx.x * blockDim.x + threadIdx.x;
    if (i < n4) out[i] = make_float4(0.f, 0.f, 0.f, 0.f);
}

// ---------------------------------------------------------------------------
// GEMM core: 128 threads (4 warps, 2x2), CTA tile 128x128, warp tile 64x64,
// K chunk 16, 3-stage cp.async. B is fragment-prepacked (8 LDS.128/warp/chunk).
// ---------------------------------------------------------------------------
#define NCHUNK 32
#define ASTRIDE 20                       // floats per A smem row (16B aligned, bank-safe)
#define A_ST_B (128 * ASTRIDE * 4)       // 10240 bytes per stage
#define B_ST_B 8192                      // 16 n8-blocks * 512 bytes
#define SMEM_TOT (3 * (A_ST_B + B_ST_B)) // 55296

__device__ __forceinline__ void load_chunk(uint32_t sA, uint32_t sB,
                                           const float* arow, const float* bsrc,
                                           int tid)
{
    uint32_t da = sA + tid * (ASTRIDE * 4);
#pragma unroll
    for (int q = 0; q < 4; q++) cpa16(da + q * 16, arow + q * 4);
    uint32_t db = sB + tid * 64;
#pragma unroll
    for (int q = 0; q < 4; q++) cpa16(db + q * 16, bsrc + tid * 16 + q * 4);
}

__device__ __forceinline__ void compute_chunk(
    const unsigned* __restrict__ As, const uint4* __restrict__ Bs,
    int wm, int wn, int lane, float acc[4][8][4])
{
    int grp = lane >> 2, thr = lane & 3;
    uint4 bf4[8];
#pragma unroll
    for (int j = 0; j < 8; j++)
        bf4[j] = Bs[(wn * 8 + j) * 32 + lane];
#pragma unroll
    for (int kh = 0; kh < 2; kh++) {
        unsigned af[4][4];
#pragma unroll
        for (int f = 0; f < 4; f++) {
            int r0 = (wm * 64 + f * 16 + grp) * ASTRIDE + kh * 8 + thr;
            af[f][0] = As[r0];
            af[f][1] = As[r0 + 8 * ASTRIDE];
            af[f][2] = As[r0 + 4];
            af[f][3] = As[r0 + 8 * ASTRIDE + 4];
        }
#pragma unroll
        for (int f = 0; f < 4; f++)
#pragma unroll
            for (int j = 0; j < 8; j++) {
                unsigned b0 = kh ? bf4[j].z : bf4[j].x;
                unsigned b1 = kh ? bf4[j].w : bf4[j].y;
                mma_tf32(acc[f][j], af[f], b0, b1);
            }
    }
}

// Shared mainloop. arowp: per-thread A row pointer (chunk 0); bbase: packed B
// base for (chunk 0, CTA n8 range); both advance per chunk.
__device__ __forceinline__ void gemm_mainloop(
    uint32_t sb, const float* arowp, const float* bbase,
    int tid, int wm, int wn, int lane, float acc[4][8][4])
{
    uint32_t sA[3], sB[3];
#pragma unroll
    for (int s = 0; s < 3; s++) {
        sA[s] = sb + s * (A_ST_B + B_ST_B);
        sB[s] = sA[s] + A_ST_B;
    }
    // B chunk stride in floats: 64 n8-blocks * 128 floats = 8192
#pragma unroll
    for (int s = 0; s < 2; s++) {
        load_chunk(sA[s], sB[s], arowp + s * 16, bbase + (size_t)s * 8192, tid);
        CP_COMMIT();
    }
    char* smem_c;
    asm("{ .reg .u64 t; cvt.u64.u32 t, %1; cvta.shared.u64 %0, t; }"
        : "=l"(smem_c) : "r"(sb));

    for (int kt = 0; kt < NCHUNK; kt++) {
        int st = kt % 3;
        if (kt + 1 < NCHUNK) { CP_WAIT1(); } else { CP_WAIT0(); }
        __syncthreads();
        if (kt + 2 < NCHUNK) {
            int ps = (kt + 2) % 3;
            load_chunk(sA[ps], sB[ps], arowp + (kt + 2) * 16,
                       bbase + (size_t)(kt + 2) * 8192, tid);
            CP_COMMIT();
        }
        const unsigned* As = (const unsigned*)(smem_c + st * (A_ST_B + B_ST_B));
        const uint4* Bs = (const uint4*)(smem_c + st * (A_ST_B + B_ST_B) + A_ST_B);
        compute_chunk(As, Bs, wm, wn, lane, acc);
        __syncthreads();
    }
}

// ---------------------------------------------------------------------------
// GEMM1: h = tf32(gelu(gather(x) @ w1 + b1))
// grid: (n-tiles 4, m-tiles 8, groups 128), 128 threads
// ---------------------------------------------------------------------------
__global__ __launch_bounds__(128) void gemm1_v2(const float* __restrict__ b1)
{
    extern __shared__ char smem[];
    uint32_t sb = smem_u32(smem);
    int tid = threadIdx.x, lane = tid & 31, warp = tid >> 5;
    int wm = warp >> 1, wn = warp & 1;
    int g = blockIdx.z, b = g >> 4, e = g & 15;
    int m0 = blockIdx.y * 128, n0 = blockIdx.x * 128;

    int tok = g_idx[g * KCAP + m0 + tid];
    const float* arowp = g_xt + ((size_t)b * SS + tok) * DD;
    const float* bbase = g_w1p + (size_t)e * DD * DFFN + (size_t)(n0 / 8) * 128;

    float acc[4][8][4] = {};
    gemm_mainloop(sb, arowp, bbase, tid, wm, wn, lane, acc);

    int grp = lane >> 2, thr = lane & 3;
    const float* bias = b1 + e * DFFN + n0;
#pragma unroll
    for (int f = 0; f < 4; f++) {
        int mloc = wm * 64 + f * 16 + grp;
        float* H0 = g_h + ((size_t)g * KCAP + m0 + mloc) * DFFN + n0;
        float* H1 = H0 + 8 * DFFN;
#pragma unroll
        for (int j = 0; j < 8; j++) {
            int nloc = wn * 64 + j * 8 + thr * 2;
            float bv0 = bias[nloc], bv1 = bias[nloc + 1];
            float2 v0, v1;
            v0.x = rtf(gelu_tanh(acc[f][j][0] + bv0));
            v0.y = rtf(gelu_tanh(acc[f][j][1] + bv1));
            *(float2*)&H0[nloc] = v0;
            v1.x = rtf(gelu_tanh(acc[f][j][2] + bv0));
            v1.y = rtf(gelu_tanh(acc[f][j][3] + bv1));
            *(float2*)&H1[nloc] = v1;
        }
    }
}

// ---------------------------------------------------------------------------
// GEMM2: out[tok] += gate * (h @ w2 + b2)
// ---------------------------------------------------------------------------
__global__ __launch_bounds__(128) void gemm2_v2(const float* __restrict__ b2,
                                                float* __restrict__ out)
{
    extern __shared__ char smem[];
    uint32_t sb = smem_u32(smem);
    int tid = threadIdx.x, lane = tid & 31, warp = tid >> 5;
    int wm = warp >> 1, wn = warp & 1;
    int g = blockIdx.z, b = g >> 4, e = g & 15;
    int m0 = blockIdx.y * 128, n0 = blockIdx.x * 128;

    const float* arowp = g_h + ((size_t)g * KCAP + m0 + tid) * DFFN;
    const float* bbase = g_w2p + (size_t)e * DFFN * DD + (size_t)(n0 / 8) * 128;

    float acc[4][8][4] = {};
    gemm_mainloop(sb, arowp, bbase, tid, wm, wn, lane, acc);

    int grp = lane >> 2, thr = lane & 3;
    const float* bias = b2 + e * DD + n0;
    float* outB = out + (size_t)b * SS * DD;
#pragma unroll
    for (int f = 0; f < 4; f++) {
        int mloc = wm * 64 + f * 16 + grp;
        int gi = g * KCAP + m0 + mloc;
        int tok0 = g_idx[gi], tok1 = g_idx[gi + 8];
        float gt0 = g_gate[gi], gt1 = g_gate[gi + 8];
        float* o0 = outB + (size_t)tok0 * DD + n0;
        float* o1 = outB + (size_t)tok1 * DD + n0;
#pragma unroll
        for (int j = 0; j < 8; j++) {
            int nloc = wn * 64 + j * 8 + thr * 2;
            float bv0 = bias[nloc], bv1 = bias[nloc + 1];
            atomicAdd(&o0[nloc],     (acc[f][j][0] + bv0) * gt0);
            atomicAdd(&o0[nloc + 1], (acc[f][j][1] + bv1) * gt0);
            atomicAdd(&o1[nloc],     (acc[f][j][2] + bv0) * gt1);
            atomicAdd(&o1[nloc + 1], (acc[f][j][3] + bv1) * gt1);
        }
    }
}

// ---------------------------------------------------------------------------
extern "C" void kernel_launch(void* const* d_in, const int* in_sizes, int n_in,
                              void* d_out, int out_size)
{
    const float* x  = (const float*)d_in[0];
    const float* gw = (const float*)d_in[1];
    const float* w1 = (const float*)d_in[2];
    const float* b1 = (const float*)d_in[3];
    const float* w2 = (const float*)d_in[4];
    const float* b2 = (const float*)d_in[5];
    float* out = (float*)d_out;

    cudaFuncSetAttribute(gemm1_v2, cudaFuncAttributeMaxDynamicSharedMemorySize, SMEM_TOT);
    cudaFuncSetAttribute(gemm2_v2, cudaFuncAttributeMaxDynamicSharedMemorySize, SMEM_TOT);

    // fragment-prepack weights (tf32-rounded): 2^20 float4 each
    pack_w1<<<4096, 256>>>(w1);
    pack_w2<<<4096, 256>>>(w2);

    router2_kernel<<<NTOK / 32, 256>>>((const float4*)x, gw);
    topk_kernel<<<NGRP, 256>>>();

    int n4 = out_size / 4;
    zero_kernel<<<(n4 + 255) / 256, 256>>>((float4*)out, n4);

    gemm1_v2<<<dim3(DFFN / 128, KCAP / 128, NGRP), 128, SMEM_TOT>>>(b1);
    gemm2_v2<<<dim3(DD / 128, KCAP / 128, NGRP), 128, SMEM_TOT>>>(b2, out);
}

// round 9
// speedup vs baseline: 1.0817x; 1.0817x over previous
#include <cuda_runtime.h>
#include <math.h>
#include <stdint.h>

// Problem constants
#define BB   8
#define SS   8192
#define DD   512
#define EE   16
#define DFFN 512
#define KCAP 1024
#define NTOK (BB*SS)
#define NGRP (BB*EE)

// Scratch — referenced ONLY inside device code
__device__ float g_aff [NGRP * SS];
__device__ int   g_idx [NGRP * KCAP];
__device__ float g_gate[NGRP * KCAP];
__device__ float g_h   [(size_t)NGRP * KCAP * DFFN];   // 256MB, tf32-rounded
__device__ float g_xt  [(size_t)NTOK * DD];            // 128MB, x tf32-rounded
__device__ float g_w1p [(size_t)EE * DD * DFFN];       // fragment-packed, tf32
__device__ float g_w2p [(size_t)EE * DFFN * DD];       // fragment-packed, tf32

__device__ __forceinline__ unsigned f2tf32(float f)
{
    unsigned r;
    asm("cvt.rna.tf32.f32 %0, %1;" : "=r"(r) : "f"(f));
    return r;
}
__device__ __forceinline__ float rtf(float f) { return __uint_as_float(f2tf32(f)); }

__device__ __forceinline__ void cpa16(uint32_t dst, const void* src)
{
    asm volatile("cp.async.cg.shared.global [%0], [%1], 16;\n" :: "r"(dst), "l"(src));
}
#define CP_COMMIT() asm volatile("cp.async.commit_group;\n" ::: "memory")
#define CP_WAIT0()  asm volatile("cp.async.wait_group 0;\n" ::: "memory")
#define CP_WAIT1()  asm volatile("cp.async.wait_group 1;\n" ::: "memory")

__device__ __forceinline__ uint32_t smem_u32(const void* p)
{
    uint32_t a;
    asm("{ .reg .u64 t; cvta.to.shared.u64 t, %1; cvt.u32.u64 %0, t; }" : "=r"(a) : "l"(p));
    return a;
}

__device__ __forceinline__ void mma_tf32(float* c, const unsigned* a,
                                         unsigned b0, unsigned b1)
{
    asm volatile(
        "mma.sync.aligned.m16n8k8.row.col.f32.tf32.tf32.f32 "
        "{%0,%1,%2,%3}, {%4,%5,%6,%7}, {%8,%9}, {%0,%1,%2,%3};\n"
        : "+f"(c[0]), "+f"(c[1]), "+f"(c[2]), "+f"(c[3])
        : "r"(a[0]), "r"(a[1]), "r"(a[2]), "r"(a[3]), "r"(b0), "r"(b1));
}

__device__ __forceinline__ float gelu_tanh(float v)
{
    float v3 = v * v * v;
    float t = tanhf(0.7978845608028654f * (v + 0.044715f * v3));
    return 0.5f * v * (1.f + t);
}

// ---------------------------------------------------------------------------
// Weight prepack (verified in R7): fragment-major, tf32-rounded.
// packed[(((e*32 + c)*64 + n8)*32 + lane)*4 + q] = w[e][k][n],
//   k = c*16 + (lane&3) + 4q,  n = n8*8 + (lane>>2)
// ---------------------------------------------------------------------------
__global__ void pack_w1(const float* __restrict__ src)
{
    size_t i = (size_t)blockIdx.x * 256 + threadIdx.x;
    int lane = i & 31; size_t t = i >> 5;
    int n8 = t & 63; t >>= 6;
    int c = t & 31; int e = (int)(t >> 5);
    int k0 = c * 16 + (lane & 3);
    int n = n8 * 8 + (lane >> 2);
    const float* S = src + ((size_t)e * DD + k0) * DFFN + n;
    float4 v;
    v.x = rtf(S[0]);
    v.y = rtf(S[4 * DFFN]);
    v.z = rtf(S[8 * DFFN]);
    v.w = rtf(S[12 * DFFN]);
    ((float4*)g_w1p)[i] = v;
}
__global__ void pack_w2(const float* __restrict__ src)
{
    size_t i = (size_t)blockIdx.x * 256 + threadIdx.x;
    int lane = i & 31; size_t t = i >> 5;
    int n8 = t & 63; t >>= 6;
    int c = t & 31; int e = (int)(t >> 5);
    int k0 = c * 16 + (lane & 3);
    int n = n8 * 8 + (lane >> 2);
    const float* S = src + ((size_t)e * DFFN + k0) * DD + n;
    float4 v;
    v.x = rtf(S[0]);
    v.y = rtf(S[4 * DD]);
    v.z = rtf(S[8 * DD]);
    v.w = rtf(S[12 * DD]);
    ((float4*)g_w2p)[i] = v;
}

// ---------------------------------------------------------------------------
// Router — 4 tokens/warp, fused softmax + x->tf32 (unchanged from R5)
// ---------------------------------------------------------------------------
__global__ __launch_bounds__(256) void router2_kernel(
    const float4* __restrict__ x4, const float* __restrict__ gw)
{
    __shared__ float4 sgw4[EE][DD / 4];
    int tid = threadIdx.x;
    for (int i = tid; i < EE * (DD / 4); i += 256) {
        int e = i >> 7, dq = i & 127;
        float4 v;
        v.x = gw[(4 * dq + 0) * EE + e];
        v.y = gw[(4 * dq + 1) * EE + e];
        v.z = gw[(4 * dq + 2) * EE + e];
        v.w = gw[(4 * dq + 3) * EE + e];
        sgw4[e][dq] = v;
    }
    __syncthreads();

    int warp = tid >> 5, lane = tid & 31;
    int t0 = blockIdx.x * 32 + warp * 4;
    int b = t0 / SS;

    float acc[4][EE];
#pragma unroll
    for (int tt = 0; tt < 4; tt++)
#pragma unroll
        for (int e = 0; e < EE; e++) acc[tt][e] = 0.f;

#pragma unroll
    for (int q = 0; q < 4; q++) {
        int dq = lane + q * 32;
        float4 xv[4];
#pragma unroll
        for (int tt = 0; tt < 4; tt++)
            xv[tt] = x4[(size_t)(t0 + tt) * (DD / 4) + dq];
#pragma unroll
        for (int tt = 0; tt < 4; tt++) {
            float4 o;
            o.x = rtf(xv[tt].x); o.y = rtf(xv[tt].y);
            o.z = rtf(xv[tt].z); o.w = rtf(xv[tt].w);
            ((float4*)g_xt)[(size_t)(t0 + tt) * (DD / 4) + dq] = o;
        }
#pragma unroll
        for (int e = 0; e < EE; e++) {
            float4 w = sgw4[e][dq];
#pragma unroll
            for (int tt = 0; tt < 4; tt++) {
                acc[tt][e] = fmaf(xv[tt].x, w.x, acc[tt][e]);
                acc[tt][e] = fmaf(xv[tt].y, w.y, acc[tt][e]);
                acc[tt][e] = fmaf(xv[tt].z, w.z, acc[tt][e]);
                acc[tt][e] = fmaf(xv[tt].w, w.w, acc[tt][e]);
            }
        }
    }

#pragma unroll
    for (int tt = 0; tt < 4; tt++)
#pragma unroll
        for (int e = 0; e < EE; e++)
#pragma unroll
            for (int o = 16; o > 0; o >>= 1)
                acc[tt][e] += __shfl_xor_sync(0xffffffffu, acc[tt][e], o);

    int le = lane & 15;
#pragma unroll
    for (int tt = 0; tt < 4; tt++) {
        float m = acc[tt][0];
#pragma unroll
        for (int e = 1; e < EE; e++) m = fmaxf(m, acc[tt][e]);
        float v = expf(acc[tt][le] - m);
        float s = v;
#pragma unroll
        for (int o = 8; o > 0; o >>= 1)
            s += __shfl_xor_sync(0xffffffffu, s, o);
        if (lane < EE) {
            int srow = t0 + tt - b * SS;
            g_aff[((size_t)(b * EE + lane)) * SS + srow] = v * (1.f / s);
        }
    }
}

// ---------------------------------------------------------------------------
// Exact radix-select top-KCAP (unchanged)
// ---------------------------------------------------------------------------
__global__ __launch_bounds__(256) void topk_kernel()
{
    int g = blockIdx.x;
    const float* a = g_aff + (size_t)g * SS;
    int tid = threadIdx.x;

    __shared__ unsigned hist[256];
    __shared__ unsigned sPrefix, sMask, sRemain;

    if (tid == 0) { sPrefix = 0u; sMask = 0u; sRemain = KCAP; }
    __syncthreads();

    for (int pass = 3; pass >= 0; pass--) {
        for (int i = tid; i < 256; i += blockDim.x) hist[i] = 0u;
        __syncthreads();
        unsigned pfx = sPrefix, msk = sMask;
        int sh = pass * 8;
        for (int s = tid; s < SS; s += blockDim.x) {
            unsigned key = __float_as_uint(a[s]);
            if ((key & msk) == pfx)
                atomicAdd(&hist[(key >> sh) & 0xFFu], 1u);
        }
        __syncthreads();
        if (tid == 0) {
            unsigned need = sRemain, cum = 0;
            int d = 255;
            for (; d > 0; d--) {
                if (cum + hist[d] >= need) break;
                cum += hist[d];
            }
            sRemain = need - cum;
            sPrefix = pfx | ((unsigned)d << sh);
            sMask   = msk | (0xFFu << sh);
        }
        __syncthreads();
    }

    unsigned T = sPrefix;
    int kEq   = (int)sRemain;
    int cntGt = KCAP - kEq;

    __shared__ unsigned gtCnt;
    __shared__ int eqBase;
    __shared__ int warpEq[8];
    if (tid == 0) { gtCnt = 0u; eqBase = 0; }
    __syncthreads();

    int lane = tid & 31, warp = tid >> 5;
    int*   oIdx  = g_idx  + g * KCAP;
    float* oGate = g_gate + g * KCAP;

    for (int c = 0; c < SS / 256; c++) {
        int s = c * 256 + tid;
        float v = a[s];
        unsigned key = __float_as_uint(v);
        bool isGt = key > T, isEq = key == T;

        if (isGt) {
            unsigned p = atomicAdd(&gtCnt, 1u);
            oIdx[p] = s; oGate[p] = v;
        }
        unsigned bal = __ballot_sync(0xffffffffu, isEq);
        if (lane == 0) warpEq[warp] = __popc(bal);
        __syncthreads();
        if (isEq) {
            int r = eqBase;
#pragma unroll
            for (int w = 0; w < 8; w++) if (w < warp) r += warpEq[w];
            r += __popc(bal & ((1u << lane) - 1u));
            if (r < kEq) { oIdx[cntGt + r] = s; oGate[cntGt + r] = v; }
        }
        __syncthreads();
        if (tid == 0) {
            int tot = 0;
#pragma unroll
            for (int w = 0; w < 8; w++) tot += warpEq[w];
            eqBase += tot;
        }
        __syncthreads();
    }
}

// ---------------------------------------------------------------------------
// Zero output
// ---------------------------------------------------------------------------
__global__ void zero_kernel(float4* __restrict__ out, int n4)
{
    int i = blockIdx.x * blockDim.x + threadIdx.x;
    if (i < n4) out[i] = make_float4(0.f, 0.f, 0.f, 0.f);
}

// ---------------------------------------------------------------------------
// GEMM core: 256 threads (8 warps, 4m x 2n), CTA 128x128, warp tile 32x64.
// K-stage = 32 (two K16 sub-chunks), 3-stage cp.async ring, packed B.
// ---------------------------------------------------------------------------
#define NSTG 16                    // 512 / 32
#define AST 36                     // floats per A smem row (32 + 4 pad)
#define A_ST_B (128 * AST * 4)     // 18432 B
#define B_ST_B (2 * 2048 * 4)      // 16384 B (two packed K16 chunks x 16 n8-blk)
#define STG_B  (A_ST_B + B_ST_B)   // 34816 B
#define SMEM_TOT (3 * STG_B)       // 104448 B

// Per-stage loads: A rows (tid>>1), half (tid&1); B contiguous packed slices.
// Gmem packed-B chunk stride = 8192 floats (64 n8-blocks x 128 floats).
__device__ __forceinline__ void load_stage(uint32_t sbase, const float* asrc,
                                           const float* bsrc, int s, int tid)
{
    uint32_t da = sbase + (tid >> 1) * (AST * 4) + (tid & 1) * 64;
    const float* ap = asrc + s * 32;
#pragma unroll
    for (int q = 0; q < 4; q++) cpa16(da + q * 16, ap + q * 4);

    uint32_t db = sbase + A_ST_B + tid * 32;
    const float* bp = bsrc + (size_t)s * 16384 + tid * 8;   // chunk 2s slice
    cpa16(db, bp);
    cpa16(db + 16, bp + 4);
    uint32_t db1 = db + 8192;                // second K16 chunk smem slot
    const float* bp1 = bp + 8192;            // chunk 2s+1 (FIX: stride 8192)
    cpa16(db1, bp1);
    cpa16(db1 + 16, bp1 + 4);
}

__device__ __forceinline__ void compute_sub(
    const unsigned* __restrict__ As, const uint4* __restrict__ Bs4,
    int sub, int wm, int wn, int grp, int thr, int lane, float acc[2][8][4])
{
    const uint4* Bc = Bs4 + sub * 512;
    uint4 bf4[8];
#pragma unroll
    for (int j = 0; j < 8; j++)
        bf4[j] = Bc[(wn * 8 + j) * 32 + lane];
#pragma unroll
    for (int s2 = 0; s2 < 2; s2++) {
        int kc = sub * 16 + s2 * 8 + thr;
        unsigned af[2][4];
#pragma unroll
        for (int f = 0; f < 2; f++) {
            int r0 = (wm * 32 + f * 16 + grp) * AST;
            af[f][0] = As[r0 + kc];
            af[f][1] = As[r0 + 8 * AST + kc];
            af[f][2] = As[r0 + kc + 4];
            af[f][3] = As[r0 + 8 * AST + kc + 4];
        }
#pragma unroll
        for (int f = 0; f < 2; f++)
#pragma unroll
            for (int j = 0; j < 8; j++) {
                unsigned b0 = s2 ? bf4[j].z : bf4[j].x;
                unsigned b1 = s2 ? bf4[j].w : bf4[j].y;
                mma_tf32(acc[f][j], af[f], b0, b1);
            }
    }
}

__device__ __forceinline__ void gemm_mainloop(
    uint32_t sb, const float* asrc, const float* bsrc,
    int tid, int wm, int wn, int grp, int thr, int lane, float acc[2][8][4])
{
    load_stage(sb, asrc, bsrc, 0, tid); CP_COMMIT();
    load_stage(sb + STG_B, asrc, bsrc, 1, tid); CP_COMMIT();

    char* smem_c;
    asm("{ .reg .u64 t; cvt.u64.u32 t, %1; cvta.shared.u64 %0, t; }"
        : "=l"(smem_c) : "r"(sb));

    for (int s = 0; s < NSTG; s++) {
        if (s + 1 < NSTG) { CP_WAIT1(); } else { CP_WAIT0(); }
        __syncthreads();
        if (s + 2 < NSTG) {
            load_stage(sb + ((s + 2) % 3) * STG_B, asrc, bsrc, s + 2, tid);
            CP_COMMIT();
        }
        const unsigned* As = (const unsigned*)(smem_c + (s % 3) * STG_B);
        const uint4* Bs4 = (const uint4*)(smem_c + (s % 3) * STG_B + A_ST_B);
        compute_sub(As, Bs4, 0, wm, wn, grp, thr, lane, acc);
        compute_sub(As, Bs4, 1, wm, wn, grp, thr, lane, acc);
    }
}

// ---------------------------------------------------------------------------
// GEMM1: h = tf32(gelu(gather(x) @ w1 + b1))
// ---------------------------------------------------------------------------
__global__ __launch_bounds__(256, 2) void gemm1_v3(const float* __restrict__ b1)
{
    extern __shared__ char smem[];
    uint32_t sb = smem_u32(smem);
    int tid = threadIdx.x, lane = tid & 31, warp = tid >> 5;
    int wm = warp >> 1, wn = warp & 1;
    int grp = lane >> 2, thr = lane & 3;
    int g = blockIdx.z, b = g >> 4, e = g & 15;
    int m0 = blockIdx.y * 128, n0 = blockIdx.x * 128;

    int tok = g_idx[g * KCAP + m0 + (tid >> 1)];
    const float* asrc = g_xt + ((size_t)b * SS + tok) * DD + (tid & 1) * 16;
    const float* bsrc = g_w1p + (size_t)e * DD * DFFN + (size_t)(n0 / 8) * 128;

    float acc[2][8][4] = {};
    gemm_mainloop(sb, asrc, bsrc, tid, wm, wn, grp, thr, lane, acc);

    const float* bias = b1 + e * DFFN + n0;
#pragma unroll
    for (int f = 0; f < 2; f++) {
        int mloc = wm * 32 + f * 16 + grp;
        float* H0 = g_h + ((size_t)g * KCAP + m0 + mloc) * DFFN + n0;
        float* H1 = H0 + 8 * DFFN;
#pragma unroll
        for (int j = 0; j < 8; j++) {
            int nloc = wn * 64 + j * 8 + thr * 2;
            float bv0 = bias[nloc], bv1 = bias[nloc + 1];
            float2 v0, v1;
            v0.x = rtf(gelu_tanh(acc[f][j][0] + bv0));
            v0.y = rtf(gelu_tanh(acc[f][j][1] + bv1));
            *(float2*)&H0[nloc] = v0;
            v1.x = rtf(gelu_tanh(acc[f][j][2] + bv0));
            v1.y = rtf(gelu_tanh(acc[f][j][3] + bv1));
            *(float2*)&H1[nloc] = v1;
        }
    }
}

// ---------------------------------------------------------------------------
// GEMM2: out[tok] += gate * (h @ w2 + b2)
// ---------------------------------------------------------------------------
__global__ __launch_bounds__(256, 2) void gemm2_v3(const float* __restrict__ b2,
                                                   float* __restrict__ out)
{
    extern __shared__ char smem[];
    uint32_t sb = smem_u32(smem);
    int tid = threadIdx.x, lane = tid & 31, warp = tid >> 5;
    int wm = warp >> 1, wn = warp & 1;
    int grp = lane >> 2, thr = lane & 3;
    int g = blockIdx.z, b = g >> 4, e = g & 15;
    int m0 = blockIdx.y * 128, n0 = blockIdx.x * 128;

    const float* asrc = g_h + ((size_t)g * KCAP + m0 + (tid >> 1)) * DFFN
                        + (tid & 1) * 16;
    const float* bsrc = g_w2p + (size_t)e * DFFN * DD + (size_t)(n0 / 8) * 128;

    float acc[2][8][4] = {};
    gemm_mainloop(sb, asrc, bsrc, tid, wm, wn, grp, thr, lane, acc);

    const float* bias = b2 + e * DD + n0;
    float* outB = out + (size_t)b * SS * DD;
#pragma unroll
    for (int f = 0; f < 2; f++) {
        int mloc = wm * 32 + f * 16 + grp;
        int gi = g * KCAP + m0 + mloc;
        int tok0 = g_idx[gi], tok1 = g_idx[gi + 8];
        float gt0 = g_gate[gi], gt1 = g_gate[gi + 8];
        float* o0 = outB + (size_t)tok0 * DD + n0;
        float* o1 = outB + (size_t)tok1 * DD + n0;
#pragma unroll
        for (int j = 0; j < 8; j++) {
            int nloc = wn * 64 + j * 8 + thr * 2;
            float bv0 = bias[nloc], bv1 = bias[nloc + 1];
            atomicAdd(&o0[nloc],     (acc[f][j][0] + bv0) * gt0);
            atomicAdd(&o0[nloc + 1], (acc[f][j][1] + bv1) * gt0);
            atomicAdd(&o1[nloc],     (acc[f][j][2] + bv0) * gt1);
            atomicAdd(&o1[nloc + 1], (acc[f][j][3] + bv1) * gt1);
        }
    }
}

// ---------------------------------------------------------------------------
extern "C" void kernel_launch(void* const* d_in, const int* in_sizes, int n_in,
                              void* d_out, int out_size)
{
    const float* x  = (const float*)d_in[0];
    const float* gw = (const float*)d_in[1];
    const float* w1 = (const float*)d_in[2];
    const float* b1 = (const float*)d_in[3];
    const float* w2 = (const float*)d_in[4];
    const float* b2 = (const float*)d_in[5];
    float* out = (float*)d_out;

    cudaFuncSetAttribute(gemm1_v3, cudaFuncAttributeMaxDynamicSharedMemorySize, SMEM_TOT);
    cudaFuncSetAttribute(gemm2_v3, cudaFuncAttributeMaxDynamicSharedMemorySize, SMEM_TOT);

    pack_w1<<<4096, 256>>>(w1);
    pack_w2<<<4096, 256>>>(w2);

    router2_kernel<<<NTOK / 32, 256>>>((const float4*)x, gw);
    topk_kernel<<<NGRP, 256>>>();

    int n4 = out_size / 4;
    zero_kernel<<<(n4 + 255) / 256, 256>>>((float4*)out, n4);

    gemm1_v3<<<dim3(DFFN / 128, KCAP / 128, NGRP), 256, SMEM_TOT>>>(b1);
    gemm2_v3<<<dim3(DD / 128, KCAP / 128, NGRP), 256, SMEM_TOT>>>(b2, out);
}

// round 11
// speedup vs baseline: 1.5727x; 1.4540x over previous
#include <cuda_runtime.h>
#include <cuda_fp16.h>
#include <math.h>
#include <stdint.h>

// Problem constants
#define BB   8
#define SS   8192
#define DD   512
#define EE   16
#define DFFN 512
#define KCAP 1024
#define NTOK (BB*SS)
#define NGRP (BB*EE)

// Scratch — referenced ONLY inside device code
__device__ float  g_aff [NGRP * SS];
__device__ int    g_idx [NGRP * KCAP];
__device__ float  g_gate[NGRP * KCAP];
__device__ __half g_h   [(size_t)NGRP * KCAP * DFFN];   // 128MB, fp16
__device__ __half g_xt  [(size_t)NTOK * DD];            // 64MB, x fp16
__device__ __half g_w1t [(size_t)EE * DFFN * DD];       // transposed [e][n][k]
__device__ __half g_w2t [(size_t)EE * DD * DFFN];       // transposed [e][n][k]

__device__ __forceinline__ void cpa16(uint32_t dst, const void* src)
{
    asm volatile("cp.async.cg.shared.global [%0], [%1], 16;\n" :: "r"(dst), "l"(src));
}
#define CP_COMMIT() asm volatile("cp.async.commit_group;\n" ::: "memory")
#define CP_WAIT0()  asm volatile("cp.async.wait_group 0;\n" ::: "memory")

__device__ __forceinline__ uint32_t smem_u32(const void* p)
{
    uint32_t a;
    asm("{ .reg .u64 t; cvta.to.shared.u64 t, %1; cvt.u32.u64 %0, t; }" : "=r"(a) : "l"(p));
    return a;
}

// fp16 MMA: m16n8k16, row.col, fp32 accumulate
__device__ __forceinline__ void mma_f16(float* c, const unsigned* a,
                                        unsigned b0, unsigned b1)
{
    asm volatile(
        "mma.sync.aligned.m16n8k16.row.col.f32.f16.f16.f32 "
        "{%0,%1,%2,%3}, {%4,%5,%6,%7}, {%8,%9}, {%0,%1,%2,%3};\n"
        : "+f"(c[0]), "+f"(c[1]), "+f"(c[2]), "+f"(c[3])
        : "r"(a[0]), "r"(a[1]), "r"(a[2]), "r"(a[3]), "r"(b0), "r"(b1));
}

__device__ __forceinline__ float gelu_tanh(float v)
{
    float v3 = v * v * v;
    float t = tanhf(0.7978845608028654f * (v + 0.044715f * v3));
    return 0.5f * v * (1.f + t);
}

// ---------------------------------------------------------------------------
// Transpose weights per expert to [e][n][k], fp16-rounded
// ---------------------------------------------------------------------------
__global__ void tr_w1_kernel(const float* __restrict__ src)
{
    __shared__ float tile[32][33];
    int e = blockIdx.z;
    const float* S = src + (size_t)e * DD * DFFN;
    __half* Dp = g_w1t + (size_t)e * DFFN * DD;
    int x = blockIdx.x * 32 + threadIdx.x;              // n
#pragma unroll
    for (int r = 0; r < 4; r++) {
        int y = blockIdx.y * 32 + threadIdx.y + r * 8;  // k
        tile[threadIdx.y + r * 8][threadIdx.x] = S[(size_t)y * DFFN + x];
    }
    __syncthreads();
    int xo = blockIdx.y * 32 + threadIdx.x;             // k
#pragma unroll
    for (int r = 0; r < 4; r++) {
        int yo = blockIdx.x * 32 + threadIdx.y + r * 8; // n
        Dp[(size_t)yo * DD + xo] = __float2half_rn(tile[threadIdx.x][threadIdx.y + r * 8]);
    }
}
__global__ void tr_w2_kernel(const float* __restrict__ src)
{
    __shared__ float tile[32][33];
    int e = blockIdx.z;
    const float* S = src + (size_t)e * DFFN * DD;
    __half* Dp = g_w2t + (size_t)e * DD * DFFN;
    int x = blockIdx.x * 32 + threadIdx.x;
#pragma unroll
    for (int r = 0; r < 4; r++) {
        int y = blockIdx.y * 32 + threadIdx.y + r * 8;
        tile[threadIdx.y + r * 8][threadIdx.x] = S[(size_t)y * DD + x];
    }
    __syncthreads();
    int xo = blockIdx.y * 32 + threadIdx.x;
#pragma unroll
    for (int r = 0; r < 4; r++) {
        int yo = blockIdx.x * 32 + threadIdx.y + r * 8;
        Dp[(size_t)yo * DFFN + xo] = __float2half_rn(tile[threadIdx.x][threadIdx.y + r * 8]);
    }
}

// ---------------------------------------------------------------------------
// Router — 4 tokens/warp, fused softmax + x->fp16
// ---------------------------------------------------------------------------
__global__ __launch_bounds__(256) void router2_kernel(
    const float4* __restrict__ x4, const float* __restrict__ gw)
{
    __shared__ float4 sgw4[EE][DD / 4];
    int tid = threadIdx.x;
    for (int i = tid; i < EE * (DD / 4); i += 256) {
        int e = i >> 7, dq = i & 127;
        float4 v;
        v.x = gw[(4 * dq + 0) * EE + e];
        v.y = gw[(4 * dq + 1) * EE + e];
        v.z = gw[(4 * dq + 2) * EE + e];
        v.w = gw[(4 * dq + 3) * EE + e];
        sgw4[e][dq] = v;
    }
    __syncthreads();

    int warp = tid >> 5, lane = tid & 31;
    int t0 = blockIdx.x * 32 + warp * 4;
    int b = t0 / SS;

    float acc[4][EE];
#pragma unroll
    for (int tt = 0; tt < 4; tt++)
#pragma unroll
        for (int e = 0; e < EE; e++) acc[tt][e] = 0.f;

#pragma unroll
    for (int q = 0; q < 4; q++) {
        int dq = lane + q * 32;
        float4 xv[4];
#pragma unroll
        for (int tt = 0; tt < 4; tt++)
            xv[tt] = x4[(size_t)(t0 + tt) * (DD / 4) + dq];
#pragma unroll
        for (int tt = 0; tt < 4; tt++) {
            __half2 h0 = __floats2half2_rn(xv[tt].x, xv[tt].y);
            __half2 h1 = __floats2half2_rn(xv[tt].z, xv[tt].w);
            uint2 pk; pk.x = *(unsigned*)&h0; pk.y = *(unsigned*)&h1;
            ((uint2*)g_xt)[(size_t)(t0 + tt) * (DD / 4) + dq] = pk;
        }
#pragma unroll
        for (int e = 0; e < EE; e++) {
            float4 w = sgw4[e][dq];
#pragma unroll
            for (int tt = 0; tt < 4; tt++) {
                acc[tt][e] = fmaf(xv[tt].x, w.x, acc[tt][e]);
                acc[tt][e] = fmaf(xv[tt].y, w.y, acc[tt][e]);
                acc[tt][e] = fmaf(xv[tt].z, w.z, acc[tt][e]);
                acc[tt][e] = fmaf(xv[tt].w, w.w, acc[tt][e]);
            }
        }
    }

#pragma unroll
    for (int tt = 0; tt < 4; tt++)
#pragma unroll
        for (int e = 0; e < EE; e++)
#pragma unroll
            for (int o = 16; o > 0; o >>= 1)
                acc[tt][e] += __shfl_xor_sync(0xffffffffu, acc[tt][e], o);

    int le = lane & 15;
#pragma unroll
    for (int tt = 0; tt < 4; tt++) {
        float m = acc[tt][0];
#pragma unroll
        for (int e = 1; e < EE; e++) m = fmaxf(m, acc[tt][e]);
        float v = expf(acc[tt][le] - m);
        float s = v;
#pragma unroll
        for (int o = 8; o > 0; o >>= 1)
            s += __shfl_xor_sync(0xffffffffu, s, o);
        if (lane < EE) {
            int srow = t0 + tt - b * SS;
            g_aff[((size_t)(b * EE + lane)) * SS + srow] = v * (1.f / s);
        }
    }
}

// ---------------------------------------------------------------------------
// Exact radix-select top-KCAP (unchanged)
// ---------------------------------------------------------------------------
__global__ __launch_bounds__(256) void topk_kernel()
{
    int g = blockIdx.x;
    const float* a = g_aff + (size_t)g * SS;
    int tid = threadIdx.x;

    __shared__ unsigned hist[256];
    __shared__ unsigned sPrefix, sMask, sRemain;

    if (tid == 0) { sPrefix = 0u; sMask = 0u; sRemain = KCAP; }
    __syncthreads();

    for (int pass = 3; pass >= 0; pass--) {
        for (int i = tid; i < 256; i += blockDim.x) hist[i] = 0u;
        __syncthreads();
        unsigned pfx = sPrefix, msk = sMask;
        int sh = pass * 8;
        for (int s = tid; s < SS; s += blockDim.x) {
            unsigned key = __float_as_uint(a[s]);
            if ((key & msk) == pfx)
                atomicAdd(&hist[(key >> sh) & 0xFFu], 1u);
        }
        __syncthreads();
        if (tid == 0) {
            unsigned need = sRemain, cum = 0;
            int d = 255;
            for (; d > 0; d--) {
                if (cum + hist[d] >= need) break;
                cum += hist[d];
            }
            sRemain = need - cum;
            sPrefix = pfx | ((unsigned)d << sh);
            sMask   = msk | (0xFFu << sh);
        }
        __syncthreads();
    }

    unsigned T = sPrefix;
    int kEq   = (int)sRemain;
    int cntGt = KCAP - kEq;

    __shared__ unsigned gtCnt;
    __shared__ int eqBase;
    __shared__ int warpEq[8];
    if (tid == 0) { gtCnt = 0u; eqBase = 0; }
    __syncthreads();

    int lane = tid & 31, warp = tid >> 5;
    int*   oIdx  = g_idx  + g * KCAP;
    float* oGate = g_gate + g * KCAP;

    for (int c = 0; c < SS / 256; c++) {
        int s = c * 256 + tid;
        float v = a[s];
        unsigned key = __float_as_uint(v);
        bool isGt = key > T, isEq = key == T;

        if (isGt) {
            unsigned p = atomicAdd(&gtCnt, 1u);
            oIdx[p] = s; oGate[p] = v;
        }
        unsigned bal = __ballot_sync(0xffffffffu, isEq);
        if (lane == 0) warpEq[warp] = __popc(bal);
        __syncthreads();
        if (isEq) {
            int r = eqBase;
#pragma unroll
            for (int w = 0; w < 8; w++) if (w < warp) r += warpEq[w];
            r += __popc(bal & ((1u << lane) - 1u));
            if (r < kEq) { oIdx[cntGt + r] = s; oGate[cntGt + r] = v; }
        }
        __syncthreads();
        if (tid == 0) {
            int tot = 0;
#pragma unroll
            for (int w = 0; w < 8; w++) tot += warpEq[w];
            eqBase += tot;
        }
        __syncthreads();
    }
}

// ---------------------------------------------------------------------------
// Zero output
// ---------------------------------------------------------------------------
__global__ void zero_kernel(float4* __restrict__ out, int n4)
{
    int i = blockIdx.x * blockDim.x + threadIdx.x;
    if (i < n4) out[i] = make_float4(0.f, 0.f, 0.f, 0.f);
}

// ---------------------------------------------------------------------------
// FP16 GEMM core: 256 threads (8 warps, 4m x 2n), CTA 128x128, warp 32x64.
// K chunk 16, 2-stage cp.async double buffer (R5-proven structure).
// Smem rows: 16 halves used + pad, stride 48 B.
// ---------------------------------------------------------------------------
#define NSTG 32                    // 512 / 16
#define RSB 48                     // row stride bytes in smem
#define T_ST_B (128 * RSB)         // 6144 B per operand per stage
#define STG_B  (2 * T_ST_B)        // 12288 B per stage (A + B)

// arow/brow already point at this thread's row base (row = tid>>1).
__device__ __forceinline__ void load_stage2(
    uint32_t sbase, const __half* arow, const __half* brow, int k0, int tid)
{
    int h = tid & 1;
    cpa16(sbase + (tid >> 1) * RSB + h * 16, arow + k0 + h * 8);
    cpa16(sbase + T_ST_B + (tid >> 1) * RSB + h * 16, brow + k0 + h * 8);
}

__device__ __forceinline__ void compute_chunk(
    const char* __restrict__ sm, int wm, int wn, int grp, int thr,
    float acc[2][8][4])
{
    const char* A = sm;
    const char* B = sm + T_ST_B;
    unsigned af[2][4];
#pragma unroll
    for (int f = 0; f < 2; f++) {
        int r = wm * 32 + f * 16 + grp;
        af[f][0] = *(const unsigned*)(A + r * RSB + thr * 4);
        af[f][1] = *(const unsigned*)(A + (r + 8) * RSB + thr * 4);
        af[f][2] = *(const unsigned*)(A + r * RSB + 16 + thr * 4);
        af[f][3] = *(const unsigned*)(A + (r + 8) * RSB + 16 + thr * 4);
    }
#pragma unroll
    for (int j = 0; j < 8; j++) {
        int n = wn * 64 + j * 8 + grp;
        unsigned b0 = *(const unsigned*)(B + n * RSB + thr * 4);
        unsigned b1 = *(const unsigned*)(B + n * RSB + 16 + thr * 4);
        mma_f16(acc[0][j], af[0], b0, b1);
        mma_f16(acc[1][j], af[1], b0, b1);
    }
}

__device__ __forceinline__ void gemm_mainloop(
    char* sm, const __half* arow, const __half* brow,
    int tid, int wm, int wn, int grp, int thr, float acc[2][8][4])
{
    uint32_t sb = smem_u32(sm);
    load_stage2(sb, arow, brow, 0, tid);
    CP_COMMIT();

    for (int s = 0; s < NSTG; s++) {
        CP_WAIT0();
        __syncthreads();
        if (s + 1 < NSTG) {
            load_stage2(sb + ((s + 1) & 1) * STG_B, arow, brow, (s + 1) * 16, tid);
            CP_COMMIT();
        }
        compute_chunk(sm + (s & 1) * STG_B, wm, wn, grp, thr, acc);
        __syncthreads();
    }
}

// ---------------------------------------------------------------------------
// GEMM1: h = fp16(gelu(gather(x) @ w1 + b1))
// ---------------------------------------------------------------------------
__global__ __launch_bounds__(256, 2) void gemm1_h(const float* __restrict__ b1)
{
    __shared__ char sm[2 * STG_B];
    int tid = threadIdx.x, lane = tid & 31, warp = tid >> 5;
    int wm = warp >> 1, wn = warp & 1;
    int grp = lane >> 2, thr = lane & 3;
    int g = blockIdx.z, b = g >> 4, e = g & 15;
    int m0 = blockIdx.y * 128, n0 = blockIdx.x * 128;

    int tok = g_idx[g * KCAP + m0 + (tid >> 1)];
    const __half* arow = g_xt + ((size_t)b * SS + tok) * DD;
    const __half* brow = g_w1t + (size_t)e * DFFN * DD
                         + (size_t)(n0 + (tid >> 1)) * DD;

    float acc[2][8][4] = {};
    gemm_mainloop(sm, arow, brow, tid, wm, wn, grp, thr, acc);

    const float* bias = b1 + e * DFFN + n0;
#pragma unroll
    for (int f = 0; f < 2; f++) {
        int mloc = wm * 32 + f * 16 + grp;
        __half* H0 = g_h + ((size_t)g * KCAP + m0 + mloc) * DFFN + n0;
        __half* H1 = H0 + 8 * DFFN;
#pragma unroll
        for (int j = 0; j < 8; j++) {
            int nloc = wn * 64 + j * 8 + thr * 2;
            float bv0 = bias[nloc], bv1 = bias[nloc + 1];
            __half2 v0 = __floats2half2_rn(gelu_tanh(acc[f][j][0] + bv0),
                                           gelu_tanh(acc[f][j][1] + bv1));
            *(__half2*)&H0[nloc] = v0;
            __half2 v1 = __floats2half2_rn(gelu_tanh(acc[f][j][2] + bv0),
                                           gelu_tanh(acc[f][j][3] + bv1));
            *(__half2*)&H1[nloc] = v1;
        }
    }
}

// ---------------------------------------------------------------------------
// GEMM2: out[tok] += gate * (h @ w2 + b2)
// ---------------------------------------------------------------------------
__global__ __launch_bounds__(256, 2) void gemm2_h(const float* __restrict__ b2,
                                                  float* __restrict__ out)
{
    __shared__ char sm[2 * STG_B];
    int tid = threadIdx.x, lane = tid & 31, warp = tid >> 5;
    int wm = warp >> 1, wn = warp & 1;
    int grp = lane >> 2, thr = lane & 3;
    int g = blockIdx.z, b = g >> 4, e = g & 15;
    int m0 = blockIdx.y * 128, n0 = blockIdx.x * 128;

    const __half* arow = g_h + ((size_t)g * KCAP + m0 + (tid >> 1)) * DFFN;
    const __half* brow = g_w2t + (size_t)e * DD * DFFN
                         + (size_t)(n0 + (tid >> 1)) * DFFN;

    float acc[2][8][4] = {};
    gemm_mainloop(sm, arow, brow, tid, wm, wn, grp, thr, acc);

    const float* bias = b2 + e * DD + n0;
    float* outB = out + (size_t)b * SS * DD;
#pragma unroll
    for (int f = 0; f < 2; f++) {
        int mloc = wm * 32 + f * 16 + grp;
        int gi = g * KCAP + m0 + mloc;
        int tok0 = g_idx[gi], tok1 = g_idx[gi + 8];
        float gt0 = g_gate[gi], gt1 = g_gate[gi + 8];
        float* o0 = outB + (size_t)tok0 * DD + n0;
        float* o1 = outB + (size_t)tok1 * DD + n0;
#pragma unroll
        for (int j = 0; j < 8; j++) {
            int nloc = wn * 64 + j * 8 + thr * 2;
            float bv0 = bias[nloc], bv1 = bias[nloc + 1];
            atomicAdd(&o0[nloc],     (acc[f][j][0] + bv0) * gt0);
            atomicAdd(&o0[nloc + 1], (acc[f][j][1] + bv1) * gt0);
            atomicAdd(&o1[nloc],     (acc[f][j][2] + bv0) * gt1);
            atomicAdd(&o1[nloc + 1], (acc[f][j][3] + bv1) * gt1);
        }
    }
}

// ---------------------------------------------------------------------------
extern "C" void kernel_launch(void* const* d_in, const int* in_sizes, int n_in,
                              void* d_out, int out_size)
{
    const float* x  = (const float*)d_in[0];
    const float* gw = (const float*)d_in[1];
    const float* w1 = (const float*)d_in[2];
    const float* b1 = (const float*)d_in[3];
    const float* w2 = (const float*)d_in[4];
    const float* b2 = (const float*)d_in[5];
    float* out = (float*)d_out;

    dim3 trb(32, 8);
    tr_w1_kernel<<<dim3(DFFN / 32, DD / 32, EE), trb>>>(w1);
    tr_w2_kernel<<<dim3(DD / 32, DFFN / 32, EE), trb>>>(w2);

    router2_kernel<<<NTOK / 32, 256>>>((const float4*)x, gw);
    topk_kernel<<<NGRP, 256>>>();

    int n4 = out_size / 4;
    zero_kernel<<<(n4 + 255) / 256, 256>>>((float4*)out, n4);

    gemm1_h<<<dim3(DFFN / 128, KCAP / 128, NGRP), 256>>>(b1);
    gemm2_h<<<dim3(DD / 128, KCAP / 128, NGRP), 256>>>(b2, out);
}

// round 12
// speedup vs baseline: 1.6839x; 1.0707x over previous
#include <cuda_runtime.h>
#include <cuda_fp16.h>
#include <math.h>
#include <stdint.h>

// Problem constants
#define BB   8
#define SS   8192
#define DD   512
#define EE   16
#define DFFN 512
#define KCAP 1024
#define NTOK (BB*SS)
#define NGRP (BB*EE)

// Scratch — referenced ONLY inside device code
__device__ float  g_aff [NGRP * SS];
__device__ int    g_idx [NGRP * KCAP];
__device__ float  g_gate[NGRP * KCAP];
__device__ __half g_h   [(size_t)NGRP * KCAP * DFFN];   // 128MB, fp16
__device__ __half g_xt  [(size_t)NTOK * DD];            // 64MB, x fp16
__device__ __half g_w1t [(size_t)EE * DFFN * DD];       // transposed [e][n][k]
__device__ __half g_w2t [(size_t)EE * DD * DFFN];       // transposed [e][n][k]

__device__ __forceinline__ void cpa16(uint32_t dst, const void* src)
{
    asm volatile("cp.async.cg.shared.global [%0], [%1], 16;\n" :: "r"(dst), "l"(src));
}
#define CP_COMMIT() asm volatile("cp.async.commit_group;\n" ::: "memory")
#define CP_WAIT0()  asm volatile("cp.async.wait_group 0;\n" ::: "memory")

__device__ __forceinline__ uint32_t smem_u32(const void* p)
{
    uint32_t a;
    asm("{ .reg .u64 t; cvta.to.shared.u64 t, %1; cvt.u32.u64 %0, t; }" : "=r"(a) : "l"(p));
    return a;
}

// fp16 MMA: m16n8k16, row.col, fp32 accumulate
__device__ __forceinline__ void mma_f16(float* c, const unsigned* a,
                                        unsigned b0, unsigned b1)
{
    asm volatile(
        "mma.sync.aligned.m16n8k16.row.col.f32.f16.f16.f32 "
        "{%0,%1,%2,%3}, {%4,%5,%6,%7}, {%8,%9}, {%0,%1,%2,%3};\n"
        : "+f"(c[0]), "+f"(c[1]), "+f"(c[2]), "+f"(c[3])
        : "r"(a[0]), "r"(a[1]), "r"(a[2]), "r"(a[3]), "r"(b0), "r"(b1));
}

__device__ __forceinline__ void ldsm_x4(unsigned* r, uint32_t addr)
{
    asm volatile("ldmatrix.sync.aligned.m8n8.x4.shared.b16 {%0,%1,%2,%3}, [%4];"
                 : "=r"(r[0]), "=r"(r[1]), "=r"(r[2]), "=r"(r[3]) : "r"(addr));
}

__device__ __forceinline__ float gelu_tanh(float v)
{
    float v3 = v * v * v;
    float t = tanhf(0.7978845608028654f * (v + 0.044715f * v3));
    return 0.5f * v * (1.f + t);
}

// ---------------------------------------------------------------------------
// Transpose weights per expert to [e][n][k], fp16-rounded
// ---------------------------------------------------------------------------
__global__ void tr_w1_kernel(const float* __restrict__ src)
{
    __shared__ float tile[32][33];
    int e = blockIdx.z;
    const float* S = src + (size_t)e * DD * DFFN;
    __half* Dp = g_w1t + (size_t)e * DFFN * DD;
    int x = blockIdx.x * 32 + threadIdx.x;              // n
#pragma unroll
    for (int r = 0; r < 4; r++) {
        int y = blockIdx.y * 32 + threadIdx.y + r * 8;  // k
        tile[threadIdx.y + r * 8][threadIdx.x] = S[(size_t)y * DFFN + x];
    }
    __syncthreads();
    int xo = blockIdx.y * 32 + threadIdx.x;             // k
#pragma unroll
    for (int r = 0; r < 4; r++) {
        int yo = blockIdx.x * 32 + threadIdx.y + r * 8; // n
        Dp[(size_t)yo * DD + xo] = __float2half_rn(tile[threadIdx.x][threadIdx.y + r * 8]);
    }
}
__global__ void tr_w2_kernel(const float* __restrict__ src)
{
    __shared__ float tile[32][33];
    int e = blockIdx.z;
    const float* S = src + (size_t)e * DFFN * DD;
    __half* Dp = g_w2t + (size_t)e * DD * DFFN;
    int x = blockIdx.x * 32 + threadIdx.x;
#pragma unroll
    for (int r = 0; r < 4; r++) {
        int y = blockIdx.y * 32 + threadIdx.y + r * 8;
        tile[threadIdx.y + r * 8][threadIdx.x] = S[(size_t)y * DD + x];
    }
    __syncthreads();
    int xo = blockIdx.y * 32 + threadIdx.x;
#pragma unroll
    for (int r = 0; r < 4; r++) {
        int yo = blockIdx.x * 32 + threadIdx.y + r * 8;
        Dp[(size_t)yo * DFFN + xo] = __float2half_rn(tile[threadIdx.x][threadIdx.y + r * 8]);
    }
}

// ---------------------------------------------------------------------------
// Router — 4 tokens/warp, fused softmax + x->fp16
// ---------------------------------------------------------------------------
__global__ __launch_bounds__(256) void router2_kernel(
    const float4* __restrict__ x4, const float* __restrict__ gw)
{
    __shared__ float4 sgw4[EE][DD / 4];
    int tid = threadIdx.x;
    for (int i = tid; i < EE * (DD / 4); i += 256) {
        int e = i >> 7, dq = i & 127;
        float4 v;
        v.x = gw[(4 * dq + 0) * EE + e];
        v.y = gw[(4 * dq + 1) * EE + e];
        v.z = gw[(4 * dq + 2) * EE + e];
        v.w = gw[(4 * dq + 3) * EE + e];
        sgw4[e][dq] = v;
    }
    __syncthreads();

    int warp = tid >> 5, lane = tid & 31;
    int t0 = blockIdx.x * 32 + warp * 4;
    int b = t0 / SS;

    float acc[4][EE];
#pragma unroll
    for (int tt = 0; tt < 4; tt++)
#pragma unroll
        for (int e = 0; e < EE; e++) acc[tt][e] = 0.f;

#pragma unroll
    for (int q = 0; q < 4; q++) {
        int dq = lane + q * 32;
        float4 xv[4];
#pragma unroll
        for (int tt = 0; tt < 4; tt++)
            xv[tt] = x4[(size_t)(t0 + tt) * (DD / 4) + dq];
#pragma unroll
        for (int tt = 0; tt < 4; tt++) {
            __half2 h0 = __floats2half2_rn(xv[tt].x, xv[tt].y);
            __half2 h1 = __floats2half2_rn(xv[tt].z, xv[tt].w);
            uint2 pk; pk.x = *(unsigned*)&h0; pk.y = *(unsigned*)&h1;
            ((uint2*)g_xt)[(size_t)(t0 + tt) * (DD / 4) + dq] = pk;
        }
#pragma unroll
        for (int e = 0; e < EE; e++) {
            float4 w = sgw4[e][dq];
#pragma unroll
            for (int tt = 0; tt < 4; tt++) {
                acc[tt][e] = fmaf(xv[tt].x, w.x, acc[tt][e]);
                acc[tt][e] = fmaf(xv[tt].y, w.y, acc[tt][e]);
                acc[tt][e] = fmaf(xv[tt].z, w.z, acc[tt][e]);
                acc[tt][e] = fmaf(xv[tt].w, w.w, acc[tt][e]);
            }
        }
    }

#pragma unroll
    for (int tt = 0; tt < 4; tt++)
#pragma unroll
        for (int e = 0; e < EE; e++)
#pragma unroll
            for (int o = 16; o > 0; o >>= 1)
                acc[tt][e] += __shfl_xor_sync(0xffffffffu, acc[tt][e], o);

    int le = lane & 15;
#pragma unroll
    for (int tt = 0; tt < 4; tt++) {
        float m = acc[tt][0];
#pragma unroll
        for (int e = 1; e < EE; e++) m = fmaxf(m, acc[tt][e]);
        float v = expf(acc[tt][le] - m);
        float s = v;
#pragma unroll
        for (int o = 8; o > 0; o >>= 1)
            s += __shfl_xor_sync(0xffffffffu, s, o);
        if (lane < EE) {
            int srow = t0 + tt - b * SS;
            g_aff[((size_t)(b * EE + lane)) * SS + srow] = v * (1.f / s);
        }
    }
}

// ---------------------------------------------------------------------------
// Exact radix-select top-KCAP (unchanged)
// ---------------------------------------------------------------------------
__global__ __launch_bounds__(256) void topk_kernel()
{
    int g = blockIdx.x;
    const float* a = g_aff + (size_t)g * SS;
    int tid = threadIdx.x;

    __shared__ unsigned hist[256];
    __shared__ unsigned sPrefix, sMask, sRemain;

    if (tid == 0) { sPrefix = 0u; sMask = 0u; sRemain = KCAP; }
    __syncthreads();

    for (int pass = 3; pass >= 0; pass--) {
        for (int i = tid; i < 256; i += blockDim.x) hist[i] = 0u;
        __syncthreads();
        unsigned pfx = sPrefix, msk = sMask;
        int sh = pass * 8;
        for (int s = tid; s < SS; s += blockDim.x) {
            unsigned key = __float_as_uint(a[s]);
            if ((key & msk) == pfx)
                atomicAdd(&hist[(key >> sh) & 0xFFu], 1u);
        }
        __syncthreads();
        if (tid == 0) {
            unsigned need = sRemain, cum = 0;
            int d = 255;
            for (; d > 0; d--) {
                if (cum + hist[d] >= need) break;
                cum += hist[d];
            }
            sRemain = need - cum;
            sPrefix = pfx | ((unsigned)d << sh);
            sMask   = msk | (0xFFu << sh);
        }
        __syncthreads();
    }

    unsigned T = sPrefix;
    int kEq   = (int)sRemain;
    int cntGt = KCAP - kEq;

    __shared__ unsigned gtCnt;
    __shared__ int eqBase;
    __shared__ int warpEq[8];
    if (tid == 0) { gtCnt = 0u; eqBase = 0; }
    __syncthreads();

    int lane = tid & 31, warp = tid >> 5;
    int*   oIdx  = g_idx  + g * KCAP;
    float* oGate = g_gate + g * KCAP;

    for (int c = 0; c < SS / 256; c++) {
        int s = c * 256 + tid;
        float v = a[s];
        unsigned key = __float_as_uint(v);
        bool isGt = key > T, isEq = key == T;

        if (isGt) {
            unsigned p = atomicAdd(&gtCnt, 1u);
            oIdx[p] = s; oGate[p] = v;
        }
        unsigned bal = __ballot_sync(0xffffffffu, isEq);
        if (lane == 0) warpEq[warp] = __popc(bal);
        __syncthreads();
        if (isEq) {
            int r = eqBase;
#pragma unroll
            for (int w = 0; w < 8; w++) if (w < warp) r += warpEq[w];
            r += __popc(bal & ((1u << lane) - 1u));
            if (r < kEq) { oIdx[cntGt + r] = s; oGate[cntGt + r] = v; }
        }
        __syncthreads();
        if (tid == 0) {
            int tot = 0;
#pragma unroll
            for (int w = 0; w < 8; w++) tot += warpEq[w];
            eqBase += tot;
        }
        __syncthreads();
    }
}

// ---------------------------------------------------------------------------
// Zero output
// ---------------------------------------------------------------------------
__global__ void zero_kernel(float4* __restrict__ out, int n4)
{
    int i = blockIdx.x * blockDim.x + threadIdx.x;
    if (i < n4) out[i] = make_float4(0.f, 0.f, 0.f, 0.f);
}

// ---------------------------------------------------------------------------
// FP16 GEMM core: 256 threads (8 warps, 4m x 2n), CTA 128x128, warp 32x64.
// K chunk 16, 2-stage cp.async double buffer, ldmatrix operand loads.
// Smem rows: 16 halves + pad, stride 48 B (ldmatrix rows stride-3 granules,
// coprime with 8 -> conflict-free phases).
// ---------------------------------------------------------------------------
#define NSTG 32                    // 512 / 16
#define RSB 48                     // row stride bytes in smem
#define T_ST_B (128 * RSB)         // 6144 B per operand per stage
#define STG_B  (2 * T_ST_B)        // 12288 B per stage (A + B)

// arow/brow already point at this thread's row base (row = tid>>1).
__device__ __forceinline__ void load_stage2(
    uint32_t sbase, const __half* arow, const __half* brow, int k0, int tid)
{
    int h = tid & 1;
    cpa16(sbase + (tid >> 1) * RSB + h * 16, arow + k0 + h * 8);
    cpa16(sbase + T_ST_B + (tid >> 1) * RSB + h * 16, brow + k0 + h * 8);
}

// aA[2]: ldmatrix addresses for the two A m16-fragments; aB[4]: for B j-pairs.
__device__ __forceinline__ void compute_chunk(
    uint32_t aA0, uint32_t aA1, const uint32_t* aB, float acc[2][8][4])
{
    unsigned a0[4], a1[4], b[16];
    ldsm_x4(a0, aA0);
    ldsm_x4(a1, aA1);
#pragma unroll
    for (int jp = 0; jp < 4; jp++)
        ldsm_x4(&b[jp * 4], aB[jp]);
#pragma unroll
    for (int jp = 0; jp < 4; jp++) {
        mma_f16(acc[0][jp * 2],     a0, b[jp * 4],     b[jp * 4 + 1]);
        mma_f16(acc[1][jp * 2],     a1, b[jp * 4],     b[jp * 4 + 1]);
        mma_f16(acc[0][jp * 2 + 1], a0, b[jp * 4 + 2], b[jp * 4 + 3]);
        mma_f16(acc[1][jp * 2 + 1], a1, b[jp * 4 + 2], b[jp * 4 + 3]);
    }
}

__device__ __forceinline__ void gemm_mainloop(
    char* sm, const __half* arow, const __half* brow,
    int tid, int wm, int wn, float acc[2][8][4])
{
    uint32_t sb = smem_u32(sm);
    int lane = tid & 31;

    // ldmatrix lane->address mapping (stage 0 base; add stage offset in loop)
    // A fragment f: tiles [m0-7,k0-7],[m8-15,k0-7],[m0-7,k8-15],[m8-15,k8-15]
    uint32_t aA[2], aB[4];
#pragma unroll
    for (int f = 0; f < 2; f++) {
        int row = wm * 32 + f * 16 + (lane & 7) + ((lane >> 3) & 1) * 8;
        aA[f] = sb + row * RSB + (lane >> 4) * 16;
    }
    // B j-pair jp: tiles [n(2jp)*8,k0-7],[same,k8-15],[n(2jp+1)*8,k0-7],[same,k8-15]
#pragma unroll
    for (int jp = 0; jp < 4; jp++) {
        int row = wn * 64 + jp * 16 + (lane & 7) + (lane >> 4) * 8;
        aB[jp] = sb + T_ST_B + row * RSB + ((lane >> 3) & 1) * 16;
    }

    load_stage2(sb, arow, brow, 0, tid);
    CP_COMMIT();

    for (int s = 0; s < NSTG; s++) {
        CP_WAIT0();
        __syncthreads();
        if (s + 1 < NSTG) {
            load_stage2(sb + ((s + 1) & 1) * STG_B, arow, brow, (s + 1) * 16, tid);
            CP_COMMIT();
        }
        uint32_t off = (s & 1) * STG_B;
        uint32_t bofs[4] = {aB[0] + off, aB[1] + off, aB[2] + off, aB[3] + off};
        compute_chunk(aA[0] + off, aA[1] + off, bofs, acc);
        // NOTE: no trailing barrier — next iteration's top barrier (after
        // CP_WAIT0) already orders this compute before buffer reuse.
    }
}

// ---------------------------------------------------------------------------
// GEMM1: h = fp16(gelu(gather(x) @ w1 + b1))
// ---------------------------------------------------------------------------
__global__ __launch_bounds__(256, 2) void gemm1_h(const float* __restrict__ b1)
{
    __shared__ char sm[2 * STG_B];
    int tid = threadIdx.x, lane = tid & 31, warp = tid >> 5;
    int wm = warp >> 1, wn = warp & 1;
    int grp = lane >> 2, thr = lane & 3;
    int g = blockIdx.z, b = g >> 4, e = g & 15;
    int m0 = blockIdx.y * 128, n0 = blockIdx.x * 128;

    int tok = g_idx[g * KCAP + m0 + (tid >> 1)];
    const __half* arow = g_xt + ((size_t)b * SS + tok) * DD;
    const __half* brow = g_w1t + (size_t)e * DFFN * DD
                         + (size_t)(n0 + (tid >> 1)) * DD;

    float acc[2][8][4] = {};
    gemm_mainloop(sm, arow, brow, tid, wm, wn, acc);

    const float* bias = b1 + e * DFFN + n0;
#pragma unroll
    for (int f = 0; f < 2; f++) {
        int mloc = wm * 32 + f * 16 + grp;
        __half* H0 = g_h + ((size_t)g * KCAP + m0 + mloc) * DFFN + n0;
        __half* H1 = H0 + 8 * DFFN;
#pragma unroll
        for (int j = 0; j < 8; j++) {
            int nloc = wn * 64 + j * 8 + thr * 2;
            float bv0 = bias[nloc], bv1 = bias[nloc + 1];
            __half2 v0 = __floats2half2_rn(gelu_tanh(acc[f][j][0] + bv0),
                                           gelu_tanh(acc[f][j][1] + bv1));
            *(__half2*)&H0[nloc] = v0;
            __half2 v1 = __floats2half2_rn(gelu_tanh(acc[f][j][2] + bv0),
                                           gelu_tanh(acc[f][j][3] + bv1));
            *(__half2*)&H1[nloc] = v1;
        }
    }
}

// ---------------------------------------------------------------------------
// GEMM2: out[tok] += gate * (h @ w2 + b2)
// ---------------------------------------------------------------------------
__global__ __launch_bounds__(256, 2) void gemm2_h(const float* __restrict__ b2,
                                                  float* __restrict__ out)
{
    __shared__ char sm[2 * STG_B];
    int tid = threadIdx.x, lane = tid & 31, warp = tid >> 5;
    int wm = warp >> 1, wn = warp & 1;
    int grp = lane >> 2, thr = lane & 3;
    int g = blockIdx.z, b = g >> 4, e = g & 15;
    int m0 = blockIdx.y * 128, n0 = blockIdx.x * 128;

    const __half* arow = g_h + ((size_t)g * KCAP + m0 + (tid >> 1)) * DFFN;
    const __half* brow = g_w2t + (size_t)e * DD * DFFN
                         + (size_t)(n0 + (tid >> 1)) * DFFN;

    float acc[2][8][4] = {};
    gemm_mainloop(sm, arow, brow, tid, wm, wn, acc);

    const float* bias = b2 + e * DD + n0;
    float* outB = out + (size_t)b * SS * DD;
#pragma unroll
    for (int f = 0; f < 2; f++) {
        int mloc = wm * 32 + f * 16 + grp;
        int gi = g * KCAP + m0 + mloc;
        int tok0 = g_idx[gi], tok1 = g_idx[gi + 8];
        float gt0 = g_gate[gi], gt1 = g_gate[gi + 8];
        float* o0 = outB + (size_t)tok0 * DD + n0;
        float* o1 = outB + (size_t)tok1 * DD + n0;
#pragma unroll
        for (int j = 0; j < 8; j++) {
            int nloc = wn * 64 + j * 8 + thr * 2;
            float bv0 = bias[nloc], bv1 = bias[nloc + 1];
            atomicAdd(&o0[nloc],     (acc[f][j][0] + bv0) * gt0);
            atomicAdd(&o0[nloc + 1], (acc[f][j][1] + bv1) * gt0);
            atomicAdd(&o1[nloc],     (acc[f][j][2] + bv0) * gt1);
            atomicAdd(&o1[nloc + 1], (acc[f][j][3] + bv1) * gt1);
        }
    }
}

// ---------------------------------------------------------------------------
extern "C" void kernel_launch(void* const* d_in, const int* in_sizes, int n_in,
                              void* d_out, int out_size)
{
    const float* x  = (const float*)d_in[0];
    const float* gw = (const float*)d_in[1];
    const float* w1 = (const float*)d_in[2];
    const float* b1 = (const float*)d_in[3];
    const float* w2 = (const float*)d_in[4];
    const float* b2 = (const float*)d_in[5];
    float* out = (float*)d_out;

    dim3 trb(32, 8);
    tr_w1_kernel<<<dim3(DFFN / 32, DD / 32, EE), trb>>>(w1);
    tr_w2_kernel<<<dim3(DD / 32, DFFN / 32, EE), trb>>>(w2);

    router2_kernel<<<NTOK / 32, 256>>>((const float4*)x, gw);
    topk_kernel<<<NGRP, 256>>>();

    int n4 = out_size / 4;
    zero_kernel<<<(n4 + 255) / 256, 256>>>((float4*)out, n4);

    gemm1_h<<<dim3(DFFN / 128, KCAP / 128, NGRP), 256>>>(b1);
    gemm2_h<<<dim3(DD / 128, KCAP / 128, NGRP), 256>>>(b2, out);
}

// round 13
// speedup vs baseline: 1.9416x; 1.1530x over previous
#include <cuda_runtime.h>
#include <cuda_fp16.h>
#include <math.h>
#include <stdint.h>

// Problem constants
#define BB   8
#define SS   8192
#define DD   512
#define EE   16
#define DFFN 512
#define KCAP 1024
#define NTOK (BB*SS)
#define NGRP (BB*EE)

// Scratch — referenced ONLY inside device code
__device__ float  g_aff [NGRP * SS];
__device__ int    g_idx [NGRP * KCAP];
__device__ float  g_gate[NGRP * KCAP];
__device__ __half g_h   [(size_t)NGRP * KCAP * DFFN];   // 128MB, fp16
__device__ __half g_xt  [(size_t)NTOK * DD];            // 64MB, x fp16
__device__ __half g_w1t [(size_t)EE * DFFN * DD];       // transposed [e][n][k]
__device__ __half g_w2t [(size_t)EE * DD * DFFN];       // transposed [e][n][k]

__device__ __forceinline__ void cpa16(uint32_t dst, const void* src)
{
    asm volatile("cp.async.cg.shared.global [%0], [%1], 16;\n" :: "r"(dst), "l"(src));
}
#define CP_COMMIT() asm volatile("cp.async.commit_group;\n" ::: "memory")
#define CP_WAIT0()  asm volatile("cp.async.wait_group 0;\n" ::: "memory")
#define CP_WAIT1()  asm volatile("cp.async.wait_group 1;\n" ::: "memory")
#define CP_WAIT2()  asm volatile("cp.async.wait_group 2;\n" ::: "memory")

__device__ __forceinline__ uint32_t smem_u32(const void* p)
{
    uint32_t a;
    asm("{ .reg .u64 t; cvta.to.shared.u64 t, %1; cvt.u32.u64 %0, t; }" : "=r"(a) : "l"(p));
    return a;
}

// fp16 MMA: m16n8k16, row.col, fp32 accumulate
__device__ __forceinline__ void mma_f16(float* c, const unsigned* a,
                                        unsigned b0, unsigned b1)
{
    asm volatile(
        "mma.sync.aligned.m16n8k16.row.col.f32.f16.f16.f32 "
        "{%0,%1,%2,%3}, {%4,%5,%6,%7}, {%8,%9}, {%0,%1,%2,%3};\n"
        : "+f"(c[0]), "+f"(c[1]), "+f"(c[2]), "+f"(c[3])
        : "r"(a[0]), "r"(a[1]), "r"(a[2]), "r"(a[3]), "r"(b0), "r"(b1));
}

__device__ __forceinline__ void ldsm_x4(unsigned* r, uint32_t addr)
{
    asm volatile("ldmatrix.sync.aligned.m8n8.x4.shared.b16 {%0,%1,%2,%3}, [%4];"
                 : "=r"(r[0]), "=r"(r[1]), "=r"(r[2]), "=r"(r[3]) : "r"(addr));
}

__device__ __forceinline__ float gelu_tanh(float v)
{
    float v3 = v * v * v;
    float t = tanhf(0.7978845608028654f * (v + 0.044715f * v3));
    return 0.5f * v * (1.f + t);
}

// ---------------------------------------------------------------------------
// Transpose weights per expert to [e][n][k], fp16-rounded
// ---------------------------------------------------------------------------
__global__ void tr_w1_kernel(const float* __restrict__ src)
{
    __shared__ float tile[32][33];
    int e = blockIdx.z;
    const float* S = src + (size_t)e * DD * DFFN;
    __half* Dp = g_w1t + (size_t)e * DFFN * DD;
    int x = blockIdx.x * 32 + threadIdx.x;              // n
#pragma unroll
    for (int r = 0; r < 4; r++) {
        int y = blockIdx.y * 32 + threadIdx.y + r * 8;  // k
        tile[threadIdx.y + r * 8][threadIdx.x] = S[(size_t)y * DFFN + x];
    }
    __syncthreads();
    int xo = blockIdx.y * 32 + threadIdx.x;             // k
#pragma unroll
    for (int r = 0; r < 4; r++) {
        int yo = blockIdx.x * 32 + threadIdx.y + r * 8; // n
        Dp[(size_t)yo * DD + xo] = __float2half_rn(tile[threadIdx.x][threadIdx.y + r * 8]);
    }
}
__global__ void tr_w2_kernel(const float* __restrict__ src)
{
    __shared__ float tile[32][33];
    int e = blockIdx.z;
    const float* S = src + (size_t)e * DFFN * DD;
    __half* Dp = g_w2t + (size_t)e * DD * DFFN;
    int x = blockIdx.x * 32 + threadIdx.x;
#pragma unroll
    for (int r = 0; r < 4; r++) {
        int y = blockIdx.y * 32 + threadIdx.y + r * 8;
        tile[threadIdx.y + r * 8][threadIdx.x] = S[(size_t)y * DD + x];
    }
    __syncthreads();
    int xo = blockIdx.y * 32 + threadIdx.x;
#pragma unroll
    for (int r = 0; r < 4; r++) {
        int yo = blockIdx.x * 32 + threadIdx.y + r * 8;
        Dp[(size_t)yo * DFFN + xo] = __float2half_rn(tile[threadIdx.x][threadIdx.y + r * 8]);
    }
}

// ---------------------------------------------------------------------------
// Router — 4 tokens/warp, fused softmax + x->fp16
// ---------------------------------------------------------------------------
__global__ __launch_bounds__(256) void router2_kernel(
    const float4* __restrict__ x4, const float* __restrict__ gw)
{
    __shared__ float4 sgw4[EE][DD / 4];
    int tid = threadIdx.x;
    for (int i = tid; i < EE * (DD / 4); i += 256) {
        int e = i >> 7, dq = i & 127;
        float4 v;
        v.x = gw[(4 * dq + 0) * EE + e];
        v.y = gw[(4 * dq + 1) * EE + e];
        v.z = gw[(4 * dq + 2) * EE + e];
        v.w = gw[(4 * dq + 3) * EE + e];
        sgw4[e][dq] = v;
    }
    __syncthreads();

    int warp = tid >> 5, lane = tid & 31;
    int t0 = blockIdx.x * 32 + warp * 4;
    int b = t0 / SS;

    float acc[4][EE];
#pragma unroll
    for (int tt = 0; tt < 4; tt++)
#pragma unroll
        for (int e = 0; e < EE; e++) acc[tt][e] = 0.f;

#pragma unroll
    for (int q = 0; q < 4; q++) {
        int dq = lane + q * 32;
        float4 xv[4];
#pragma unroll
        for (int tt = 0; tt < 4; tt++)
            xv[tt] = x4[(size_t)(t0 + tt) * (DD / 4) + dq];
#pragma unroll
        for (int tt = 0; tt < 4; tt++) {
            __half2 h0 = __floats2half2_rn(xv[tt].x, xv[tt].y);
            __half2 h1 = __floats2half2_rn(xv[tt].z, xv[tt].w);
            uint2 pk; pk.x = *(unsigned*)&h0; pk.y = *(unsigned*)&h1;
            ((uint2*)g_xt)[(size_t)(t0 + tt) * (DD / 4) + dq] = pk;
        }
#pragma unroll
        for (int e = 0; e < EE; e++) {
            float4 w = sgw4[e][dq];
#pragma unroll
            for (int tt = 0; tt < 4; tt++) {
                acc[tt][e] = fmaf(xv[tt].x, w.x, acc[tt][e]);
                acc[tt][e] = fmaf(xv[tt].y, w.y, acc[tt][e]);
                acc[tt][e] = fmaf(xv[tt].z, w.z, acc[tt][e]);
                acc[tt][e] = fmaf(xv[tt].w, w.w, acc[tt][e]);
            }
        }
    }

#pragma unroll
    for (int tt = 0; tt < 4; tt++)
#pragma unroll
        for (int e = 0; e < EE; e++)
#pragma unroll
            for (int o = 16; o > 0; o >>= 1)
                acc[tt][e] += __shfl_xor_sync(0xffffffffu, acc[tt][e], o);

    int le = lane & 15;
#pragma unroll
    for (int tt = 0; tt < 4; tt++) {
        float m = acc[tt][0];
#pragma unroll
        for (int e = 1; e < EE; e++) m = fmaxf(m, acc[tt][e]);
        float v = expf(acc[tt][le] - m);
        float s = v;
#pragma unroll
        for (int o = 8; o > 0; o >>= 1)
            s += __shfl_xor_sync(0xffffffffu, s, o);
        if (lane < EE) {
            int srow = t0 + tt - b * SS;
            g_aff[((size_t)(b * EE + lane)) * SS + srow] = v * (1.f / s);
        }
    }
}

// ---------------------------------------------------------------------------
// Exact radix-select top-KCAP (unchanged)
// ---------------------------------------------------------------------------
__global__ __launch_bounds__(256) void topk_kernel()
{
    int g = blockIdx.x;
    const float* a = g_aff + (size_t)g * SS;
    int tid = threadIdx.x;

    __shared__ unsigned hist[256];
    __shared__ unsigned sPrefix, sMask, sRemain;

    if (tid == 0) { sPrefix = 0u; sMask = 0u; sRemain = KCAP; }
    __syncthreads();

    for (int pass = 3; pass >= 0; pass--) {
        for (int i = tid; i < 256; i += blockDim.x) hist[i] = 0u;
        __syncthreads();
        unsigned pfx = sPrefix, msk = sMask;
        int sh = pass * 8;
        for (int s = tid; s < SS; s += blockDim.x) {
            unsigned key = __float_as_uint(a[s]);
            if ((key & msk) == pfx)
                atomicAdd(&hist[(key >> sh) & 0xFFu], 1u);
        }
        __syncthreads();
        if (tid == 0) {
            unsigned need = sRemain, cum = 0;
            int d = 255;
            for (; d > 0; d--) {
                if (cum + hist[d] >= need) break;
                cum += hist[d];
            }
            sRemain = need - cum;
            sPrefix = pfx | ((unsigned)d << sh);
            sMask   = msk | (0xFFu << sh);
        }
        __syncthreads();
    }

    unsigned T = sPrefix;
    int kEq   = (int)sRemain;
    int cntGt = KCAP - kEq;

    __shared__ unsigned gtCnt;
    __shared__ int eqBase;
    __shared__ int warpEq[8];
    if (tid == 0) { gtCnt = 0u; eqBase = 0; }
    __syncthreads();

    int lane = tid & 31, warp = tid >> 5;
    int*   oIdx  = g_idx  + g * KCAP;
    float* oGate = g_gate + g * KCAP;

    for (int c = 0; c < SS / 256; c++) {
        int s = c * 256 + tid;
        float v = a[s];
        unsigned key = __float_as_uint(v);
        bool isGt = key > T, isEq = key == T;

        if (isGt) {
            unsigned p = atomicAdd(&gtCnt, 1u);
            oIdx[p] = s; oGate[p] = v;
        }
        unsigned bal = __ballot_sync(0xffffffffu, isEq);
        if (lane == 0) warpEq[warp] = __popc(bal);
        __syncthreads();
        if (isEq) {
            int r = eqBase;
#pragma unroll
            for (int w = 0; w < 8; w++) if (w < warp) r += warpEq[w];
            r += __popc(bal & ((1u << lane) - 1u));
            if (r < kEq) { oIdx[cntGt + r] = s; oGate[cntGt + r] = v; }
        }
        __syncthreads();
        if (tid == 0) {
            int tot = 0;
#pragma unroll
            for (int w = 0; w < 8; w++) tot += warpEq[w];
            eqBase += tot;
        }
        __syncthreads();
    }
}

// ---------------------------------------------------------------------------
// Zero output
// ---------------------------------------------------------------------------
__global__ void zero_kernel(float4* __restrict__ out, int n4)
{
    int i = blockIdx.x * blockDim.x + threadIdx.x;
    if (i < n4) out[i] = make_float4(0.f, 0.f, 0.f, 0.f);
}

// ---------------------------------------------------------------------------
// FP16 GEMM core: 256 threads (8 warps, 4m x 2n), CTA 128x128, warp 32x64.
// K chunk 16, 4-stage cp.async pipeline (prefetch distance 3), ldmatrix loads.
// ---------------------------------------------------------------------------
#define NSTG 32                    // 512 / 16
#define RSB 48                     // row stride bytes in smem
#define T_ST_B (128 * RSB)         // 6144 B per operand per stage
#define STG_B  (2 * T_ST_B)        // 12288 B per stage (A + B)
// total static smem: 4 * STG_B = 49152 B (= 48KB static limit)

// arow/brow already point at this thread's row base (row = tid>>1).
__device__ __forceinline__ void load_stage2(
    uint32_t sbase, const __half* arow, const __half* brow, int k0, int tid)
{
    int h = tid & 1;
    cpa16(sbase + (tid >> 1) * RSB + h * 16, arow + k0 + h * 8);
    cpa16(sbase + T_ST_B + (tid >> 1) * RSB + h * 16, brow + k0 + h * 8);
}

// aA[2]: ldmatrix addresses for the two A m16-fragments; aB[4]: for B j-pairs.
__device__ __forceinline__ void compute_chunk(
    uint32_t aA0, uint32_t aA1, const uint32_t* aB, float acc[2][8][4])
{
    unsigned a0[4], a1[4], b[16];
    ldsm_x4(a0, aA0);
    ldsm_x4(a1, aA1);
#pragma unroll
    for (int jp = 0; jp < 4; jp++)
        ldsm_x4(&b[jp * 4], aB[jp]);
#pragma unroll
    for (int jp = 0; jp < 4; jp++) {
        mma_f16(acc[0][jp * 2],     a0, b[jp * 4],     b[jp * 4 + 1]);
        mma_f16(acc[1][jp * 2],     a1, b[jp * 4],     b[jp * 4 + 1]);
        mma_f16(acc[0][jp * 2 + 1], a0, b[jp * 4 + 2], b[jp * 4 + 3]);
        mma_f16(acc[1][jp * 2 + 1], a1, b[jp * 4 + 2], b[jp * 4 + 3]);
    }
}

__device__ __forceinline__ void gemm_mainloop(
    char* sm, const __half* arow, const __half* brow,
    int tid, int wm, int wn, float acc[2][8][4])
{
    uint32_t sb = smem_u32(sm);
    int lane = tid & 31;

    uint32_t aA[2], aB[4];
#pragma unroll
    for (int f = 0; f < 2; f++) {
        int row = wm * 32 + f * 16 + (lane & 7) + ((lane >> 3) & 1) * 8;
        aA[f] = sb + row * RSB + (lane >> 4) * 16;
    }
#pragma unroll
    for (int jp = 0; jp < 4; jp++) {
        int row = wn * 64 + jp * 16 + (lane & 7) + (lane >> 4) * 8;
        aB[jp] = sb + T_ST_B + row * RSB + ((lane >> 3) & 1) * 16;
    }

    // prefetch stages 0..2
#pragma unroll
    for (int s = 0; s < 3; s++) {
        load_stage2(sb + s * STG_B, arow, brow, s * 16, tid);
        CP_COMMIT();
    }

    for (int s = 0; s < NSTG; s++) {
        // wait until stage s complete (taper at tail)
        if (s < NSTG - 2)      { CP_WAIT2(); }
        else if (s == NSTG - 2){ CP_WAIT1(); }
        else                   { CP_WAIT0(); }
        __syncthreads();
        if (s + 3 < NSTG) {
            load_stage2(sb + ((s + 3) & 3) * STG_B, arow, brow, (s + 3) * 16, tid);
            CP_COMMIT();
        }
        uint32_t off = (s & 3) * STG_B;
        uint32_t bofs[4] = {aB[0] + off, aB[1] + off, aB[2] + off, aB[3] + off};
        compute_chunk(aA[0] + off, aA[1] + off, bofs, acc);
        // no trailing barrier: next iteration's barrier orders buffer reuse
        // (load s+3 targets buffer (s-1)&3, computed in the previous iteration)
    }
}

// ---------------------------------------------------------------------------
// GEMM1: h = fp16(gelu(gather(x) @ w1 + b1))
// ---------------------------------------------------------------------------
__global__ __launch_bounds__(256, 2) void gemm1_h(const float* __restrict__ b1)
{
    __shared__ char sm[4 * STG_B];
    int tid = threadIdx.x, lane = tid & 31, warp = tid >> 5;
    int wm = warp >> 1, wn = warp & 1;
    int grp = lane >> 2, thr = lane & 3;
    int g = blockIdx.z, b = g >> 4, e = g & 15;
    int m0 = blockIdx.y * 128, n0 = blockIdx.x * 128;

    int tok = g_idx[g * KCAP + m0 + (tid >> 1)];
    const __half* arow = g_xt + ((size_t)b * SS + tok) * DD;
    const __half* brow = g_w1t + (size_t)e * DFFN * DD
                         + (size_t)(n0 + (tid >> 1)) * DD;

    float acc[2][8][4] = {};
    gemm_mainloop(sm, arow, brow, tid, wm, wn, acc);

    const float* bias = b1 + e * DFFN + n0;
#pragma unroll
    for (int f = 0; f < 2; f++) {
        int mloc = wm * 32 + f * 16 + grp;
        __half* H0 = g_h + ((size_t)g * KCAP + m0 + mloc) * DFFN + n0;
        __half* H1 = H0 + 8 * DFFN;
#pragma unroll
        for (int j = 0; j < 8; j++) {
            int nloc = wn * 64 + j * 8 + thr * 2;
            float bv0 = bias[nloc], bv1 = bias[nloc + 1];
            __half2 v0 = __floats2half2_rn(gelu_tanh(acc[f][j][0] + bv0),
                                           gelu_tanh(acc[f][j][1] + bv1));
            *(__half2*)&H0[nloc] = v0;
            __half2 v1 = __floats2half2_rn(gelu_tanh(acc[f][j][2] + bv0),
                                           gelu_tanh(acc[f][j][3] + bv1));
            *(__half2*)&H1[nloc] = v1;
        }
    }
}

// ---------------------------------------------------------------------------
// GEMM2: out[tok] += gate * (h @ w2 + b2)
// ---------------------------------------------------------------------------
__global__ __launch_bounds__(256, 2) void gemm2_h(const float* __restrict__ b2,
                                                  float* __restrict__ out)
{
    __shared__ char sm[4 * STG_B];
    int tid = threadIdx.x, lane = tid & 31, warp = tid >> 5;
    int wm = warp >> 1, wn = warp & 1;
    int grp = lane >> 2, thr = lane & 3;
    int g = blockIdx.z, b = g >> 4, e = g & 15;
    int m0 = blockIdx.y * 128, n0 = blockIdx.x * 128;

    const __half* arow = g_h + ((size_t)g * KCAP + m0 + (tid >> 1)) * DFFN;
    const __half* brow = g_w2t + (size_t)e * DD * DFFN
                         + (size_t)(n0 + (tid >> 1)) * DFFN;

    float acc[2][8][4] = {};
    gemm_mainloop(sm, arow, brow, tid, wm, wn, acc);

    const float* bias = b2 + e * DD + n0;
    float* outB = out + (size_t)b * SS * DD;
#pragma unroll
    for (int f = 0; f < 2; f++) {
        int mloc = wm * 32 + f * 16 + grp;
        int gi = g * KCAP + m0 + mloc;
        int tok0 = g_idx[gi], tok1 = g_idx[gi + 8];
        float gt0 = g_gate[gi], gt1 = g_gate[gi + 8];
        float* o0 = outB + (size_t)tok0 * DD + n0;
        float* o1 = outB + (size_t)tok1 * DD + n0;
#pragma unroll
        for (int j = 0; j < 8; j++) {
            int nloc = wn * 64 + j * 8 + thr * 2;
            float bv0 = bias[nloc], bv1 = bias[nloc + 1];
            atomicAdd(&o0[nloc],     (acc[f][j][0] + bv0) * gt0);
            atomicAdd(&o0[nloc + 1], (acc[f][j][1] + bv1) * gt0);
            atomicAdd(&o1[nloc],     (acc[f][j][2] + bv0) * gt1);
            atomicAdd(&o1[nloc + 1], (acc[f][j][3] + bv1) * gt1);
        }
    }
}

// ---------------------------------------------------------------------------
extern "C" void kernel_launch(void* const* d_in, const int* in_sizes, int n_in,
                              void* d_out, int out_size)
{
    const float* x  = (const float*)d_in[0];
    const float* gw = (const float*)d_in[1];
    const float* w1 = (const float*)d_in[2];
    const float* b1 = (const float*)d_in[3];
    const float* w2 = (const float*)d_in[4];
    const float* b2 = (const float*)d_in[5];
    float* out = (float*)d_out;

    dim3 trb(32, 8);
    tr_w1_kernel<<<dim3(DFFN / 32, DD / 32, EE), trb>>>(w1);
    tr_w2_kernel<<<dim3(DD / 32, DFFN / 32, EE), trb>>>(w2);

    router2_kernel<<<NTOK / 32, 256>>>((const float4*)x, gw);
    topk_kernel<<<NGRP, 256>>>();

    int n4 = out_size / 4;
    zero_kernel<<<(n4 + 255) / 256, 256>>>((float4*)out, n4);

    gemm1_h<<<dim3(DFFN / 128, KCAP / 128, NGRP), 256>>>(b1);
    gemm2_h<<<dim3(DD / 128, KCAP / 128, NGRP), 256>>>(b2, out);
}

// round 14
// speedup vs baseline: 1.9751x; 1.0173x over previous
#include <cuda_runtime.h>
#include <cuda_fp16.h>
#include <math.h>
#include <stdint.h>

// Problem constants
#define BB   8
#define SS   8192
#define DD   512
#define EE   16
#define DFFN 512
#define KCAP 1024
#define NTOK (BB*SS)
#define NGRP (BB*EE)

// Scratch — referenced ONLY inside device code
__device__ float  g_aff [NGRP * SS];
__device__ int    g_idx [NGRP * KCAP];
__device__ float  g_gate[NGRP * KCAP];
__device__ __half g_h   [(size_t)NGRP * KCAP * DFFN];   // 128MB, fp16
__device__ __half g_xt  [(size_t)NTOK * DD];            // 64MB, x fp16
__device__ __half g_w1t [(size_t)EE * DFFN * DD];       // transposed [e][n][k]
__device__ __half g_w2t [(size_t)EE * DD * DFFN];       // transposed [e][n][k]

__device__ __forceinline__ void cpa16(uint32_t dst, const void* src)
{
    asm volatile("cp.async.cg.shared.global [%0], [%1], 16;\n" :: "r"(dst), "l"(src));
}
#define CP_COMMIT() asm volatile("cp.async.commit_group;\n" ::: "memory")
#define CP_WAIT0()  asm volatile("cp.async.wait_group 0;\n" ::: "memory")
#define CP_WAIT1()  asm volatile("cp.async.wait_group 1;\n" ::: "memory")

__device__ __forceinline__ uint32_t smem_u32(const void* p)
{
    uint32_t a;
    asm("{ .reg .u64 t; cvta.to.shared.u64 t, %1; cvt.u32.u64 %0, t; }" : "=r"(a) : "l"(p));
    return a;
}

// fp16 MMA: m16n8k16, row.col, fp32 accumulate
__device__ __forceinline__ void mma_f16(float* c, const unsigned* a,
                                        unsigned b0, unsigned b1)
{
    asm volatile(
        "mma.sync.aligned.m16n8k16.row.col.f32.f16.f16.f32 "
        "{%0,%1,%2,%3}, {%4,%5,%6,%7}, {%8,%9}, {%0,%1,%2,%3};\n"
        : "+f"(c[0]), "+f"(c[1]), "+f"(c[2]), "+f"(c[3])
        : "r"(a[0]), "r"(a[1]), "r"(a[2]), "r"(a[3]), "r"(b0), "r"(b1));
}

__device__ __forceinline__ void ldsm_x4(unsigned* r, uint32_t addr)
{
    asm volatile("ldmatrix.sync.aligned.m8n8.x4.shared.b16 {%0,%1,%2,%3}, [%4];"
                 : "=r"(r[0]), "=r"(r[1]), "=r"(r[2]), "=r"(r[3]) : "r"(addr));
}

__device__ __forceinline__ float gelu_tanh(float v)
{
    float v3 = v * v * v;
    float t = tanhf(0.7978845608028654f * (v + 0.044715f * v3));
    return 0.5f * v * (1.f + t);
}

// ---------------------------------------------------------------------------
// Merged weight transpose: z = which*16 + e  (DD == DFFN == 512)
// ---------------------------------------------------------------------------
__global__ void tr_w_kernel(const float* __restrict__ w1,
                            const float* __restrict__ w2)
{
    __shared__ float tile[32][33];
    int z = blockIdx.z;
    int e = z & 15, which = z >> 4;
    const float* S = (which ? w2 : w1) + (size_t)e * DD * DFFN;
    __half* Dp = (which ? g_w2t : g_w1t) + (size_t)e * DD * DFFN;
    int x = blockIdx.x * 32 + threadIdx.x;
#pragma unroll
    for (int r = 0; r < 4; r++) {
        int y = blockIdx.y * 32 + threadIdx.y + r * 8;
        tile[threadIdx.y + r * 8][threadIdx.x] = S[(size_t)y * 512 + x];
    }
    __syncthreads();
    int xo = blockIdx.y * 32 + threadIdx.x;
#pragma unroll
    for (int r = 0; r < 4; r++) {
        int yo = blockIdx.x * 32 + threadIdx.y + r * 8;
        Dp[(size_t)yo * 512 + xo] = __float2half_rn(tile[threadIdx.x][threadIdx.y + r * 8]);
    }
}

// ---------------------------------------------------------------------------
// Router — 4 tokens/warp, fused softmax + x->fp16
// ---------------------------------------------------------------------------
__global__ __launch_bounds__(256) void router2_kernel(
    const float4* __restrict__ x4, const float* __restrict__ gw)
{
    __shared__ float4 sgw4[EE][DD / 4];
    int tid = threadIdx.x;
    for (int i = tid; i < EE * (DD / 4); i += 256) {
        int e = i >> 7, dq = i & 127;
        float4 v;
        v.x = gw[(4 * dq + 0) * EE + e];
        v.y = gw[(4 * dq + 1) * EE + e];
        v.z = gw[(4 * dq + 2) * EE + e];
        v.w = gw[(4 * dq + 3) * EE + e];
        sgw4[e][dq] = v;
    }
    __syncthreads();

    int warp = tid >> 5, lane = tid & 31;
    int t0 = blockIdx.x * 32 + warp * 4;
    int b = t0 / SS;

    float acc[4][EE];
#pragma unroll
    for (int tt = 0; tt < 4; tt++)
#pragma unroll
        for (int e = 0; e < EE; e++) acc[tt][e] = 0.f;

#pragma unroll
    for (int q = 0; q < 4; q++) {
        int dq = lane + q * 32;
        float4 xv[4];
#pragma unroll
        for (int tt = 0; tt < 4; tt++)
            xv[tt] = x4[(size_t)(t0 + tt) * (DD / 4) + dq];
#pragma unroll
        for (int tt = 0; tt < 4; tt++) {
            __half2 h0 = __floats2half2_rn(xv[tt].x, xv[tt].y);
            __half2 h1 = __floats2half2_rn(xv[tt].z, xv[tt].w);
            uint2 pk; pk.x = *(unsigned*)&h0; pk.y = *(unsigned*)&h1;
            ((uint2*)g_xt)[(size_t)(t0 + tt) * (DD / 4) + dq] = pk;
        }
#pragma unroll
        for (int e = 0; e < EE; e++) {
            float4 w = sgw4[e][dq];
#pragma unroll
            for (int tt = 0; tt < 4; tt++) {
                acc[tt][e] = fmaf(xv[tt].x, w.x, acc[tt][e]);
                acc[tt][e] = fmaf(xv[tt].y, w.y, acc[tt][e]);
                acc[tt][e] = fmaf(xv[tt].z, w.z, acc[tt][e]);
                acc[tt][e] = fmaf(xv[tt].w, w.w, acc[tt][e]);
            }
        }
    }

#pragma unroll
    for (int tt = 0; tt < 4; tt++)
#pragma unroll
        for (int e = 0; e < EE; e++)
#pragma unroll
            for (int o = 16; o > 0; o >>= 1)
                acc[tt][e] += __shfl_xor_sync(0xffffffffu, acc[tt][e], o);

    int le = lane & 15;
#pragma unroll
    for (int tt = 0; tt < 4; tt++) {
        float m = acc[tt][0];
#pragma unroll
        for (int e = 1; e < EE; e++) m = fmaxf(m, acc[tt][e]);
        float v = expf(acc[tt][le] - m);
        float s = v;
#pragma unroll
        for (int o = 8; o > 0; o >>= 1)
            s += __shfl_xor_sync(0xffffffffu, s, o);
        if (lane < EE) {
            int srow = t0 + tt - b * SS;
            g_aff[((size_t)(b * EE + lane)) * SS + srow] = v * (1.f / s);
        }
    }
}

// ---------------------------------------------------------------------------
// Exact radix-select top-KCAP (unchanged)
// ---------------------------------------------------------------------------
__global__ __launch_bounds__(256) void topk_kernel()
{
    int g = blockIdx.x;
    const float* a = g_aff + (size_t)g * SS;
    int tid = threadIdx.x;

    __shared__ unsigned hist[256];
    __shared__ unsigned sPrefix, sMask, sRemain;

    if (tid == 0) { sPrefix = 0u; sMask = 0u; sRemain = KCAP; }
    __syncthreads();

    for (int pass = 3; pass >= 0; pass--) {
        for (int i = tid; i < 256; i += blockDim.x) hist[i] = 0u;
        __syncthreads();
        unsigned pfx = sPrefix, msk = sMask;
        int sh = pass * 8;
        for (int s = tid; s < SS; s += blockDim.x) {
            unsigned key = __float_as_uint(a[s]);
            if ((key & msk) == pfx)
                atomicAdd(&hist[(key >> sh) & 0xFFu], 1u);
        }
        __syncthreads();
        if (tid == 0) {
            unsigned need = sRemain, cum = 0;
            int d = 255;
            for (; d > 0; d--) {
                if (cum + hist[d] >= need) break;
                cum += hist[d];
            }
            sRemain = need - cum;
            sPrefix = pfx | ((unsigned)d << sh);
            sMask   = msk | (0xFFu << sh);
        }
        __syncthreads();
    }

    unsigned T = sPrefix;
    int kEq   = (int)sRemain;
    int cntGt = KCAP - kEq;

    __shared__ unsigned gtCnt;
    __shared__ int eqBase;
    __shared__ int warpEq[8];
    if (tid == 0) { gtCnt = 0u; eqBase = 0; }
    __syncthreads();

    int lane = tid & 31, warp = tid >> 5;
    int*   oIdx  = g_idx  + g * KCAP;
    float* oGate = g_gate + g * KCAP;

    for (int c = 0; c < SS / 256; c++) {
        int s = c * 256 + tid;
        float v = a[s];
        unsigned key = __float_as_uint(v);
        bool isGt = key > T, isEq = key == T;

        if (isGt) {
            unsigned p = atomicAdd(&gtCnt, 1u);
            oIdx[p] = s; oGate[p] = v;
        }
        unsigned bal = __ballot_sync(0xffffffffu, isEq);
        if (lane == 0) warpEq[warp] = __popc(bal);
        __syncthreads();
        if (isEq) {
            int r = eqBase;
#pragma unroll
            for (int w = 0; w < 8; w++) if (w < warp) r += warpEq[w];
            r += __popc(bal & ((1u << lane) - 1u));
            if (r < kEq) { oIdx[cntGt + r] = s; oGate[cntGt + r] = v; }
        }
        __syncthreads();
        if (tid == 0) {
            int tot = 0;
#pragma unroll
            for (int w = 0; w < 8; w++) tot += warpEq[w];
            eqBase += tot;
        }
        __syncthreads();
    }
}

// ---------------------------------------------------------------------------
// Zero output
// ---------------------------------------------------------------------------
__global__ void zero_kernel(float4* __restrict__ out, int n4)
{
    int i = blockIdx.x * blockDim.x + threadIdx.x;
    if (i < n4) out[i] = make_float4(0.f, 0.f, 0.f, 0.f);
}

// ---------------------------------------------------------------------------
// FP16 GEMM core: 256 threads (8 warps, 4m x 2n), CTA 128x128, warp 32x64.
// K chunk 32, 3-stage cp.async pipeline (prefetch distance 2), ldmatrix loads.
// Smem rows: 32 halves (64B) + 16B pad, stride 80B (5 granules, coprime 8 ->
// conflict-free ldmatrix phases).
// ---------------------------------------------------------------------------
#define NSTG 16                    // 512 / 32
#define RSB 80                     // row stride bytes in smem
#define T_ST_B (128 * RSB)         // 10240 B per operand per stage
#define STG_B  (2 * T_ST_B)        // 20480 B per stage (A + B)
#define SMEM_TOT (3 * STG_B)       // 61440 B dynamic

// arow/brow point at this thread's row base (row = tid>>1); h=tid&1 covers 32B.
__device__ __forceinline__ void load_stage2(
    uint32_t sbase, const __half* arow, const __half* brow, int k0, int tid)
{
    int h = tid & 1;
    uint32_t da = sbase + (tid >> 1) * RSB + h * 32;
    const __half* ap = arow + k0 + h * 16;
    cpa16(da, ap);
    cpa16(da + 16, ap + 8);
    uint32_t db = sbase + T_ST_B + (tid >> 1) * RSB + h * 32;
    const __half* bp = brow + k0 + h * 16;
    cpa16(db, bp);
    cpa16(db + 16, bp + 8);
}

// One K16 sub-chunk: aA/aB already include stage+sub offsets.
__device__ __forceinline__ void compute_sub(
    uint32_t aA0, uint32_t aA1, uint32_t aB0, uint32_t aB1, uint32_t aB2,
    uint32_t aB3, float acc[2][8][4])
{
    unsigned a0[4], a1[4], b[16];
    ldsm_x4(a0, aA0);
    ldsm_x4(a1, aA1);
    ldsm_x4(&b[0], aB0);
    ldsm_x4(&b[4], aB1);
    ldsm_x4(&b[8], aB2);
    ldsm_x4(&b[12], aB3);
#pragma unroll
    for (int jp = 0; jp < 4; jp++) {
        mma_f16(acc[0][jp * 2],     a0, b[jp * 4],     b[jp * 4 + 1]);
        mma_f16(acc[1][jp * 2],     a1, b[jp * 4],     b[jp * 4 + 1]);
        mma_f16(acc[0][jp * 2 + 1], a0, b[jp * 4 + 2], b[jp * 4 + 3]);
        mma_f16(acc[1][jp * 2 + 1], a1, b[jp * 4 + 2], b[jp * 4 + 3]);
    }
}

__device__ __forceinline__ void gemm_mainloop(
    char* sm, const __half* arow, const __half* brow,
    int tid, int wm, int wn, float acc[2][8][4])
{
    uint32_t sb = smem_u32(sm);
    int lane = tid & 31;

    // ldmatrix base addresses (sub-chunk 0 of stage 0)
    uint32_t aA[2], aB[4];
#pragma unroll
    for (int f = 0; f < 2; f++) {
        int row = wm * 32 + f * 16 + (lane & 7) + ((lane >> 3) & 1) * 8;
        aA[f] = sb + row * RSB + (lane >> 4) * 16;
    }
#pragma unroll
    for (int jp = 0; jp < 4; jp++) {
        int row = wn * 64 + jp * 16 + (lane & 7) + (lane >> 4) * 8;
        aB[jp] = sb + T_ST_B + row * RSB + ((lane >> 3) & 1) * 16;
    }

    // prefetch stages 0,1
#pragma unroll
    for (int s = 0; s < 2; s++) {
        load_stage2(sb + s * STG_B, arow, brow, s * 32, tid);
        CP_COMMIT();
    }

    for (int s = 0; s < NSTG; s++) {
        if (s < NSTG - 1) { CP_WAIT1(); } else { CP_WAIT0(); }
        __syncthreads();
        if (s + 2 < NSTG) {
            load_stage2(sb + ((s + 2) % 3) * STG_B, arow, brow, (s + 2) * 32, tid);
            CP_COMMIT();
        }
        uint32_t off = (s % 3) * STG_B;
        compute_sub(aA[0] + off, aA[1] + off, aB[0] + off, aB[1] + off,
                    aB[2] + off, aB[3] + off, acc);
        compute_sub(aA[0] + off + 32, aA[1] + off + 32, aB[0] + off + 32,
                    aB[1] + off + 32, aB[2] + off + 32, aB[3] + off + 32, acc);
        // no trailing barrier: next iteration's barrier orders buffer reuse
    }
}

// ---------------------------------------------------------------------------
// GEMM1: h = fp16(gelu(gather(x) @ w1 + b1))
// ---------------------------------------------------------------------------
__global__ __launch_bounds__(256, 2) void gemm1_h(const float* __restrict__ b1)
{
    extern __shared__ char sm[];
    int tid = threadIdx.x, lane = tid & 31, warp = tid >> 5;
    int wm = warp >> 1, wn = warp & 1;
    int grp = lane >> 2, thr = lane & 3;
    int g = blockIdx.z, b = g >> 4, e = g & 15;
    int m0 = blockIdx.y * 128, n0 = blockIdx.x * 128;

    int tok = g_idx[g * KCAP + m0 + (tid >> 1)];
    const __half* arow = g_xt + ((size_t)b * SS + tok) * DD;
    const __half* brow = g_w1t + (size_t)e * DFFN * DD
                         + (size_t)(n0 + (tid >> 1)) * DD;

    float acc[2][8][4] = {};
    gemm_mainloop(sm, arow, brow, tid, wm, wn, acc);

    const float* bias = b1 + e * DFFN + n0;
#pragma unroll
    for (int f = 0; f < 2; f++) {
        int mloc = wm * 32 + f * 16 + grp;
        __half* H0 = g_h + ((size_t)g * KCAP + m0 + mloc) * DFFN + n0;
        __half* H1 = H0 + 8 * DFFN;
#pragma unroll
        for (int j = 0; j < 8; j++) {
            int nloc = wn * 64 + j * 8 + thr * 2;
            float bv0 = bias[nloc], bv1 = bias[nloc + 1];
            __half2 v0 = __floats2half2_rn(gelu_tanh(acc[f][j][0] + bv0),
                                           gelu_tanh(acc[f][j][1] + bv1));
            *(__half2*)&H0[nloc] = v0;
            __half2 v1 = __floats2half2_rn(gelu_tanh(acc[f][j][2] + bv0),
                                           gelu_tanh(acc[f][j][3] + bv1));
            *(__half2*)&H1[nloc] = v1;
        }
    }
}

// ---------------------------------------------------------------------------
// GEMM2: out[tok] += gate * (h @ w2 + b2)
// ---------------------------------------------------------------------------
__global__ __launch_bounds__(256, 2) void gemm2_h(const float* __restrict__ b2,
                                                  float* __restrict__ out)
{
    extern __shared__ char sm[];
    int tid = threadIdx.x, lane = tid & 31, warp = tid >> 5;
    int wm = warp >> 1, wn = warp & 1;
    int grp = lane >> 2, thr = lane & 3;
    int g = blockIdx.z, b = g >> 4, e = g & 15;
    int m0 = blockIdx.y * 128, n0 = blockIdx.x * 128;

    const __half* arow = g_h + ((size_t)g * KCAP + m0 + (tid >> 1)) * DFFN;
    const __half* brow = g_w2t + (size_t)e * DD * DFFN
                         + (size_t)(n0 + (tid >> 1)) * DFFN;

    float acc[2][8][4] = {};
    gemm_mainloop(sm, arow, brow, tid, wm, wn, acc);

    const float* bias = b2 + e * DD + n0;
    float* outB = out + (size_t)b * SS * DD;
#pragma unroll
    for (int f = 0; f < 2; f++) {
        int mloc = wm * 32 + f * 16 + grp;
        int gi = g * KCAP + m0 + mloc;
        int tok0 = g_idx[gi], tok1 = g_idx[gi + 8];
        float gt0 = g_gate[gi], gt1 = g_gate[gi + 8];
        float* o0 = outB + (size_t)tok0 * DD + n0;
        float* o1 = outB + (size_t)tok1 * DD + n0;
#pragma unroll
        for (int j = 0; j < 8; j++) {
            int nloc = wn * 64 + j * 8 + thr * 2;
            float bv0 = bias[nloc], bv1 = bias[nloc + 1];
            atomicAdd(&o0[nloc],     (acc[f][j][0] + bv0) * gt0);
            atomicAdd(&o0[nloc + 1], (acc[f][j][1] + bv1) * gt0);
            atomicAdd(&o1[nloc],     (acc[f][j][2] + bv0) * gt1);
            atomicAdd(&o1[nloc + 1], (acc[f][j][3] + bv1) * gt1);
        }
    }
}

// ---------------------------------------------------------------------------
extern "C" void kernel_launch(void* const* d_in, const int* in_sizes, int n_in,
                              void* d_out, int out_size)
{
    const float* x  = (const float*)d_in[0];
    const float* gw = (const float*)d_in[1];
    const float* w1 = (const float*)d_in[2];
    const float* b1 = (const float*)d_in[3];
    const float* w2 = (const float*)d_in[4];
    const float* b2 = (const float*)d_in[5];
    float* out = (float*)d_out;

    cudaFuncSetAttribute(gemm1_h, cudaFuncAttributeMaxDynamicSharedMemorySize, SMEM_TOT);
    cudaFuncSetAttribute(gemm2_h, cudaFuncAttributeMaxDynamicSharedMemorySize, SMEM_TOT);

    dim3 trb(32, 8);
    tr_w_kernel<<<dim3(16, 16, 2 * EE), trb>>>(w1, w2);

    router2_kernel<<<NTOK / 32, 256>>>((const float4*)x, gw);
    topk_kernel<<<NGRP, 256>>>();

    int n4 = out_size / 4;
    zero_kernel<<<(n4 + 255) / 256, 256>>>((float4*)out, n4);

    gemm1_h<<<dim3(DFFN / 128, KCAP / 128, NGRP), 256, SMEM_TOT>>>(b1);
    gemm2_h<<<dim3(DD / 128, KCAP / 128, NGRP), 256, SMEM_TOT>>>(b2, out);
}